// round 12
// baseline (speedup 1.0000x reference)
#include <cuda_runtime.h>
#include <cuda_bf16.h>
#include <cuda_fp16.h>
#include <cstdint>

#define NN 50000
#define RR 8
#define HH 128
#define CC 40
#define EE 800000
#define NZ 9           // 8 relations + root2
#define MTILES 391     // ceil(NN/128)

// ---- scratch (device globals; no allocation allowed) ----
__device__ float g_cnt[NN * RR];                       // raw counts
__device__ int g_relcnt[RR];                           // per-relation edge counts
__device__ int g_cursor[RR];                           // bucket write cursors
__device__ int2 g_ebkt[EE];                            // rel-bucketed {src, dst*8+rel}
__device__ float g_h[(size_t)NN * HH];                 // layer-1 fp32 accumulator
__device__ __half g_xr[(size_t)RR * NN * HH];          // 102.4 MB: xr in fp16
__device__ float g_h2[(size_t)NN * HH];
__device__ __nv_bfloat16 g_Ahi[(size_t)NN * HH];
__device__ __nv_bfloat16 g_Alo[(size_t)NN * HH];
__device__ __nv_bfloat16 g_Bhi[(size_t)NZ * HH * HH];  // transposed: [z][n][k]
__device__ __nv_bfloat16 g_Blo[(size_t)NZ * HH * HH];

// ================= PTX helpers =================
__device__ __forceinline__ uint32_t smem_u32(const void* p) {
    uint32_t a;
    asm("{ .reg .u64 t; cvta.to.shared.u64 t, %1; cvt.u32.u64 %0, t; }" : "=r"(a) : "l"(p));
    return a;
}
__device__ __forceinline__ void red4(float* p, float x, float y, float z, float w) {
    asm volatile("red.global.add.v4.f32 [%0], {%1,%2,%3,%4};"
                 :: "l"(p), "f"(x), "f"(y), "f"(z), "f"(w) : "memory");
}
__device__ __forceinline__ void ldsm4(uint32_t* r, uint32_t addr) {
    asm volatile("ldmatrix.sync.aligned.m8n8.x4.shared.b16 {%0,%1,%2,%3}, [%4];"
                 : "=r"(r[0]), "=r"(r[1]), "=r"(r[2]), "=r"(r[3]) : "r"(addr));
}
__device__ __forceinline__ void mma_bf16(float* d, const uint32_t* a, const uint32_t* b) {
    asm volatile(
        "mma.sync.aligned.m16n8k16.row.col.f32.bf16.bf16.f32 "
        "{%0,%1,%2,%3}, {%4,%5,%6,%7}, {%8,%9}, {%0,%1,%2,%3};"
        : "+f"(d[0]), "+f"(d[1]), "+f"(d[2]), "+f"(d[3])
        : "r"(a[0]), "r"(a[1]), "r"(a[2]), "r"(a[3]), "r"(b[0]), "r"(b[1]));
}
__device__ __forceinline__ void cp_async16(uint32_t saddr, const void* gaddr) {
    asm volatile("cp.async.cg.shared.global [%0], [%1], 16;" :: "r"(saddr), "l"(gaddr));
}
__device__ __forceinline__ void cp_async8(uint32_t saddr, const void* gaddr) {
    asm volatile("cp.async.ca.shared.global [%0], [%1], 8;" :: "r"(saddr), "l"(gaddr));
}
#define CP_COMMIT() asm volatile("cp.async.commit_group;" ::: "memory")
#define CP_WAIT(n)  asm volatile("cp.async.wait_group %0;" :: "n"(n) : "memory")

// ================= phase kernels =================
__global__ void zero_kernel() {
    size_t tid = (size_t)blockIdx.x * blockDim.x + threadIdx.x;
    size_t stride = (size_t)gridDim.x * blockDim.x;
    float4 z = make_float4(0.f, 0.f, 0.f, 0.f);
    float4* h4 = reinterpret_cast<float4*>(g_h);
    for (size_t i = tid; i < (size_t)NN * HH / 4; i += stride) h4[i] = z;
    float4* c4 = reinterpret_cast<float4*>(g_cnt);
    for (size_t i = tid; i < (size_t)NN * RR / 4; i += stride) c4[i] = z;
    if (tid < RR) g_relcnt[tid] = 0;
}

// counts per (dst,rel) + per-rel histogram (smem-aggregated)
__global__ void count_kernel(const int* __restrict__ ei, const int* __restrict__ et) {
    __shared__ int hist[RR];
    if (threadIdx.x < RR) hist[threadIdx.x] = 0;
    __syncthreads();
    int e = blockIdx.x * blockDim.x + threadIdx.x;
    if (e < EE) {
        int dst = ei[EE + e];
        int r = et[e];
        atomicAdd(&g_cnt[dst * RR + r], 1.0f);
        atomicAdd(&hist[r], 1);
    }
    __syncthreads();
    if (threadIdx.x < RR) atomicAdd(&g_relcnt[threadIdx.x], hist[threadIdx.x]);
}

// exclusive scan of 8 relation counts -> bucket cursors
__global__ void scan_kernel() {
    if (threadIdx.x == 0) {
        int run = 0;
        for (int r = 0; r < RR; r++) { g_cursor[r] = run; run += g_relcnt[r]; }
    }
}

// partition edges into per-relation buckets: g_ebkt[pos] = {src, dst*8+rel}
__global__ __launch_bounds__(256) void partition_kernel(const int* __restrict__ ei,
                                                        const int* __restrict__ et) {
    __shared__ int cnt[RR];
    __shared__ int base[RR];
    if (threadIdx.x < RR) cnt[threadIdx.x] = 0;
    __syncthreads();
    int e0 = blockIdx.x * 1024 + threadIdx.x;
    int r[4], loc[4], src[4], seg[4];
#pragma unroll
    for (int j = 0; j < 4; j++) {
        int e = e0 + j * 256;
        bool v = e < EE;
        r[j] = v ? et[e] : 0;
        src[j] = v ? ei[e] : 0;
        seg[j] = v ? (ei[EE + e] * RR + r[j]) : 0;
        loc[j] = v ? atomicAdd(&cnt[r[j]], 1) : -1;
    }
    __syncthreads();
    if (threadIdx.x < RR) base[threadIdx.x] = atomicAdd(&g_cursor[threadIdx.x], cnt[threadIdx.x]);
    __syncthreads();
#pragma unroll
    for (int j = 0; j < 4; j++) {
        if (loc[j] >= 0) g_ebkt[base[r[j]] + loc[j]] = make_int2(src[j], seg[j]);
    }
}

// layer 1 scatter: rel-bucketed edges, cp.async-staged, 16 edges per warp
__global__ __launch_bounds__(256) void scatter1_kernel(const float* __restrict__ W1) {
    extern __shared__ char smem[];
    const int wid = threadIdx.x >> 5, lane = threadIdx.x & 31;
    char* buf = smem + wid * (16 * 512);
    const int e0 = (blockIdx.x * 8 + wid) * 16;

    int2 ev = g_ebkt[e0 + (lane & 15)];
    float cw = (lane < 16) ? g_cnt[ev.y] : 1.0f;
    float winv = __frcp_rn(fmaxf(cw, 1.0f));

#pragma unroll
    for (int j = 0; j < 16; j++) {
        int srcj = __shfl_sync(0xffffffffu, ev.x, j);
        int segj = __shfl_sync(0xffffffffu, ev.y, j);
        const char* g = reinterpret_cast<const char*>(W1) +
                        ((size_t)(segj & 7) * NN + srcj) * (HH * 4) + lane * 16;
        cp_async16(smem_u32(buf + j * 512 + lane * 16), g);
    }
    CP_COMMIT();
    CP_WAIT(0);

#pragma unroll
    for (int j = 0; j < 16; j++) {
        int segj = __shfl_sync(0xffffffffu, ev.y, j);
        float wj = __shfl_sync(0xffffffffu, winv, j);
        float4 v = *reinterpret_cast<float4*>(buf + j * 512 + lane * 16);
        red4(g_h + (size_t)(segj >> 3) * HH + lane * 4,
             wj * v.x, wj * v.y, wj * v.z, wj * v.w);
    }
}

// fused: h = relu(g_h + root1 + b1) -> bf16 hi/lo split
__global__ void fin1prepA_kernel(const float* __restrict__ root1, const float* __restrict__ b1) {
    int i = blockIdx.x * blockDim.x + threadIdx.x;
    if (i >= NN * HH / 4) return;
    float4 h = reinterpret_cast<const float4*>(g_h)[i];
    float4 r = reinterpret_cast<const float4*>(root1)[i];
    float4 b = reinterpret_cast<const float4*>(b1)[i & (HH / 4 - 1)];
    float x = fmaxf(h.x + r.x + b.x, 0.f);
    float y = fmaxf(h.y + r.y + b.y, 0.f);
    float z = fmaxf(h.z + r.z + b.z, 0.f);
    float w = fmaxf(h.w + r.w + b.w, 0.f);
    __nv_bfloat16 hx = __float2bfloat16(x), hy = __float2bfloat16(y);
    __nv_bfloat16 hz = __float2bfloat16(z), hw = __float2bfloat16(w);
    __nv_bfloat16 lx = __float2bfloat16(x - __bfloat162float(hx));
    __nv_bfloat16 ly = __float2bfloat16(y - __bfloat162float(hy));
    __nv_bfloat16 lz = __float2bfloat16(z - __bfloat162float(hz));
    __nv_bfloat16 lw = __float2bfloat16(w - __bfloat162float(hw));
    __nv_bfloat162 h0 = __halves2bfloat162(hx, hy), h1 = __halves2bfloat162(hz, hw);
    __nv_bfloat162 l0 = __halves2bfloat162(lx, ly), l1 = __halves2bfloat162(lz, lw);
    uint2 ph, pl;
    ph.x = *reinterpret_cast<uint32_t*>(&h0); ph.y = *reinterpret_cast<uint32_t*>(&h1);
    pl.x = *reinterpret_cast<uint32_t*>(&l0); pl.y = *reinterpret_cast<uint32_t*>(&l1);
    reinterpret_cast<uint2*>(g_Ahi)[i] = ph;
    reinterpret_cast<uint2*>(g_Alo)[i] = pl;
}

// W2 / root2 -> transposed bf16 hi/lo:  B[z][n][k] = W[z][k][n]
__global__ void prepB_kernel(const float* __restrict__ W2, const float* __restrict__ root2) {
    int idx = blockIdx.x * blockDim.x + threadIdx.x;
    if (idx >= NZ * HH * HH) return;
    int z = idx >> 14;
    int n = (idx >> 7) & 127;
    int k = idx & 127;
    float v = (z < RR) ? W2[((size_t)z << 14) + k * HH + n] : root2[k * HH + n];
    __nv_bfloat16 hi = __float2bfloat16(v);
    __nv_bfloat16 lo = __float2bfloat16(v - __bfloat162float(hi));
    g_Bhi[idx] = hi;
    g_Blo[idx] = lo;
}

// ================= HMMA GEMM (double-buffered B via cp.async) =================
#define PITCH 136
#define PITCHB (PITCH * 2)
#define TILEB (128 * PITCHB)            // 34816 B
static constexpr int SM_AHI = 0;
static constexpr int SM_ALO = SM_AHI + TILEB;
static constexpr int SM_B0 = SM_ALO + TILEB;             // buf0: hi then lo
static constexpr int SM_B1 = SM_B0 + 2 * TILEB;          // buf1: hi then lo
static constexpr int SM_TOTAL = SM_B1 + 2 * TILEB;       // 208896 B

__device__ __forceinline__ void stage_B_async(char* smem, int buf_base, int z, int tid) {
#pragma unroll
    for (int i = 0; i < 8; i++) {
        int idx = tid + i * 256;
        int row = idx >> 4, seg = idx & 15;
        uint32_t so = row * PITCHB + seg * 16;
        const uint4* Bh = reinterpret_cast<const uint4*>(g_Bhi) + (size_t)z * 2048 + row * 16 + seg;
        const uint4* Bl = reinterpret_cast<const uint4*>(g_Blo) + (size_t)z * 2048 + row * 16 + seg;
        cp_async16(smem_u32(smem + buf_base + so), Bh);
        cp_async16(smem_u32(smem + buf_base + TILEB + so), Bl);
    }
}

__global__ __launch_bounds__(256, 1) void gemm_kernel(const float* __restrict__ b2) {
    extern __shared__ char smem[];
    uint32_t sb = smem_u32(smem);
    const int tid = threadIdx.x;
    const int wid = tid >> 5, lane = tid & 31;
    const int warp_m = (wid & 3) * 32;
    const int warp_n = (wid >> 2) * 64;
    const int row0 = blockIdx.x * 128;

    // prologue: async-stage B[0] into buf0
    stage_B_async(smem, SM_B0, 0, tid);
    CP_COMMIT();

    // ---- stage A hi/lo (once)
    {
        uint4 zz = make_uint4(0, 0, 0, 0);
#pragma unroll
        for (int i = 0; i < 8; i++) {
            int idx = tid + i * 256;
            int row = idx >> 4, seg = idx & 15;
            int gr = row0 + row;
            bool v = gr < NN;
            uint32_t so = row * PITCHB + seg * 16;
            const uint4* Ah = reinterpret_cast<const uint4*>(g_Ahi) + (size_t)gr * 16 + seg;
            const uint4* Al = reinterpret_cast<const uint4*>(g_Alo) + (size_t)gr * 16 + seg;
            *reinterpret_cast<uint4*>(smem + SM_AHI + so) = v ? *Ah : zz;
            *reinterpret_cast<uint4*>(smem + SM_ALO + so) = v ? *Al : zz;
        }
    }

    const uint32_t a_row = (uint32_t)(warp_m + (lane & 15));
    const uint32_t a_base = a_row * PITCHB + ((lane >> 4) << 3) * 2;
    const uint32_t b_n = (uint32_t)(warp_n + (lane & 7) + ((lane >> 4) << 3));
    const uint32_t b_base = b_n * PITCHB + (((lane >> 3) & 1) << 3) * 2;

    for (int z = 0; z < NZ; z++) {
        const int cur = (z & 1) ? SM_B1 : SM_B0;
        if (z + 1 < NZ) {
            stage_B_async(smem, (z & 1) ? SM_B0 : SM_B1, z + 1, tid);
            CP_COMMIT();
            CP_WAIT(1);
        } else {
            CP_WAIT(0);
        }
        __syncthreads();

        float acc[16][4];
#pragma unroll
        for (int i = 0; i < 16; i++)
#pragma unroll
            for (int j = 0; j < 4; j++) acc[i][j] = 0.f;

#pragma unroll
        for (int k = 0; k < 8; k++) {
            const uint32_t koff = (uint32_t)(k * 32);
            uint32_t ahi[2][4], alo[2][4];
#pragma unroll
            for (int mt = 0; mt < 2; mt++) {
                uint32_t ao = a_base + (uint32_t)(mt * 16) * PITCHB + koff;
                ldsm4(ahi[mt], sb + SM_AHI + ao);
                ldsm4(alo[mt], sb + SM_ALO + ao);
            }
            uint32_t bhi[8][2], blo[8][2];
#pragma unroll
            for (int ntp = 0; ntp < 4; ntp++) {
                uint32_t bo = b_base + (uint32_t)(ntp * 16) * PITCHB + koff;
                uint32_t rh[4], rl[4];
                ldsm4(rh, sb + cur + bo);
                ldsm4(rl, sb + cur + TILEB + bo);
                bhi[ntp * 2][0] = rh[0]; bhi[ntp * 2][1] = rh[1];
                bhi[ntp * 2 + 1][0] = rh[2]; bhi[ntp * 2 + 1][1] = rh[3];
                blo[ntp * 2][0] = rl[0]; blo[ntp * 2][1] = rl[1];
                blo[ntp * 2 + 1][0] = rl[2]; blo[ntp * 2 + 1][1] = rl[3];
            }
#pragma unroll
            for (int mt = 0; mt < 2; mt++)
#pragma unroll
                for (int nt = 0; nt < 8; nt++) {
                    mma_bf16(acc[mt * 8 + nt], ahi[mt], bhi[nt]);
                    mma_bf16(acc[mt * 8 + nt], ahi[mt], blo[nt]);
                    mma_bf16(acc[mt * 8 + nt], alo[mt], bhi[nt]);
                }
        }

        // ---- epilogue
        const int erow = lane >> 2;
        const int ecol0 = (lane & 3) * 2;
        if (z < RR) {
            __half* out = g_xr + (size_t)z * NN * HH;
#pragma unroll
            for (int mt = 0; mt < 2; mt++) {
                int r0 = row0 + warp_m + mt * 16 + erow;
                int r1 = r0 + 8;
                bool v0 = r0 < NN, v1 = r1 < NN;
#pragma unroll
                for (int nt = 0; nt < 8; nt++) {
                    int c = warp_n + nt * 8 + ecol0;
                    float* a4 = acc[mt * 8 + nt];
                    if (v0) {
                        __half2 o = __floats2half2_rn(a4[0], a4[1]);
                        *reinterpret_cast<__half2*>(out + (size_t)r0 * HH + c) = o;
                    }
                    if (v1) {
                        __half2 o = __floats2half2_rn(a4[2], a4[3]);
                        *reinterpret_cast<__half2*>(out + (size_t)r1 * HH + c) = o;
                    }
                }
            }
        } else {
            float* out = g_h2;
#pragma unroll
            for (int mt = 0; mt < 2; mt++) {
                int r0 = row0 + warp_m + mt * 16 + erow;
                int r1 = r0 + 8;
                bool v0 = r0 < NN, v1 = r1 < NN;
#pragma unroll
                for (int nt = 0; nt < 8; nt++) {
                    int c = warp_n + nt * 8 + ecol0;
                    float bb0 = b2[c], bb1 = b2[c + 1];
                    float* a4 = acc[mt * 8 + nt];
                    if (v0) {
                        float2 o = make_float2(a4[0] + bb0, a4[1] + bb1);
                        *reinterpret_cast<float2*>(out + (size_t)r0 * HH + c) = o;
                    }
                    if (v1) {
                        float2 o = make_float2(a4[2] + bb0, a4[3] + bb1);
                        *reinterpret_cast<float2*>(out + (size_t)r1 * HH + c) = o;
                    }
                }
            }
        }
        __syncthreads();   // all reads of cur done before it is overwritten
    }
}

// layer 2 scatter: rel-bucketed edges, cp.async-staged fp16 rows, 16 edges per warp
__global__ __launch_bounds__(256) void scatter2_kernel() {
    extern __shared__ char smem[];
    const int wid = threadIdx.x >> 5, lane = threadIdx.x & 31;
    char* buf = smem + wid * (16 * 256);
    const int e0 = (blockIdx.x * 8 + wid) * 16;

    int2 ev = g_ebkt[e0 + (lane & 15)];
    float cw = (lane < 16) ? g_cnt[ev.y] : 1.0f;
    float winv = __frcp_rn(fmaxf(cw, 1.0f));

#pragma unroll
    for (int j = 0; j < 16; j++) {
        int srcj = __shfl_sync(0xffffffffu, ev.x, j);
        int segj = __shfl_sync(0xffffffffu, ev.y, j);
        const char* g = reinterpret_cast<const char*>(g_xr) +
                        ((size_t)(segj & 7) * NN + srcj) * (HH * 2) + lane * 8;
        cp_async8(smem_u32(buf + j * 256 + lane * 8), g);
    }
    CP_COMMIT();
    CP_WAIT(0);

#pragma unroll
    for (int j = 0; j < 16; j++) {
        int segj = __shfl_sync(0xffffffffu, ev.y, j);
        float wj = __shfl_sync(0xffffffffu, winv, j);
        uint2 p = *reinterpret_cast<uint2*>(buf + j * 256 + lane * 8);
        __half2 h0 = *reinterpret_cast<__half2*>(&p.x);
        __half2 h1 = *reinterpret_cast<__half2*>(&p.y);
        float2 f0 = __half22float2(h0);
        float2 f1 = __half22float2(h1);
        red4(g_h2 + (size_t)(segj >> 3) * HH + lane * 4,
             wj * f0.x, wj * f0.y, wj * f1.x, wj * f1.y);
    }
}

// out = relu(h2) @ lin_w + lin_b
__global__ void final_kernel(const float* __restrict__ lin_w, const float* __restrict__ lin_b,
                             float* __restrict__ out) {
    __shared__ float sw[HH * CC];
    __shared__ float sh[32][HH + 1];
    int tid = threadIdx.x;
    for (int i = tid; i < HH * CC; i += 256) sw[i] = lin_w[i];
    int n0 = blockIdx.x * 32;
    for (int i = tid; i < 32 * HH; i += 256) {
        int nl = i / HH, k = i % HH;
        int n = n0 + nl;
        sh[nl][k] = (n < NN) ? fmaxf(g_h2[(size_t)n * HH + k], 0.f) : 0.f;
    }
    __syncthreads();
#pragma unroll
    for (int j = 0; j < 5; j++) {
        int idx = tid + j * 256;
        int nl = idx / CC, c = idx % CC;
        float acc = lin_b[c];
#pragma unroll
        for (int k = 0; k < HH; k++) acc = fmaf(sh[nl][k], sw[k * CC + c], acc);
        int n = n0 + nl;
        if (n < NN) out[(size_t)n * CC + c] = acc;
    }
}

// ================= launch =================
extern "C" void kernel_launch(void* const* d_in, const int* in_sizes, int n_in,
                              void* d_out, int out_size) {
    const int* ei = (const int*)d_in[0];
    const int* et = (const int*)d_in[1];
    const float* W1 = (const float*)d_in[2];
    const float* root1 = (const float*)d_in[3];
    const float* b1 = (const float*)d_in[4];
    const float* W2 = (const float*)d_in[5];
    const float* root2 = (const float*)d_in[6];
    const float* b2 = (const float*)d_in[7];
    const float* lin_w = (const float*)d_in[8];
    const float* lin_b = (const float*)d_in[9];
    float* out = (float*)d_out;

    cudaFuncSetAttribute(gemm_kernel, cudaFuncAttributeMaxDynamicSharedMemorySize, SM_TOTAL);
    cudaFuncSetAttribute(scatter1_kernel, cudaFuncAttributeMaxDynamicSharedMemorySize, 65536);

    zero_kernel<<<2048, 256>>>();
    prepB_kernel<<<(NZ * HH * HH + 255) / 256, 256>>>(W2, root2);
    count_kernel<<<(EE + 255) / 256, 256>>>(ei, et);
    scan_kernel<<<1, 32>>>();
    partition_kernel<<<(EE + 1023) / 1024, 256>>>(ei, et);
    scatter1_kernel<<<EE / 128, 256, 65536>>>(W1);     // 16 edges/warp, 8 warps/block
    fin1prepA_kernel<<<(NN * HH / 4 + 255) / 256, 256>>>(root1, b1);
    gemm_kernel<<<MTILES, 256, SM_TOTAL>>>(b2);
    scatter2_kernel<<<EE / 128, 256, 32768>>>();       // 16 edges/warp, 8 warps/block
    final_kernel<<<(NN + 31) / 32, 256>>>(lin_w, lin_b, out);
}

// round 13
// speedup vs baseline: 1.5339x; 1.5339x over previous
#include <cuda_runtime.h>
#include <cuda_bf16.h>
#include <cuda_fp16.h>
#include <cstdint>

#define NN 50000
#define RR 8
#define HH 128
#define CC 40
#define EE 800000
#define NZ 9           // 8 relations + root2
#define MTILES 391     // ceil(NN/128)

// ---- scratch (device globals; no allocation allowed) ----
__device__ float g_cnt[NN * RR];                       // raw counts
__device__ int2 g_eidx[EE];                            // packed {src, dst*8+rel}
__device__ float g_h[(size_t)NN * HH];                 // layer-1 fp32 accumulator
__device__ __half g_xr[(size_t)RR * NN * HH];          // 102.4 MB: xr in fp16
__device__ float g_h2[(size_t)NN * HH];
__device__ __nv_bfloat16 g_Ahi[(size_t)NN * HH];
__device__ __nv_bfloat16 g_Alo[(size_t)NN * HH];
__device__ __nv_bfloat16 g_Bhi[(size_t)NZ * HH * HH];  // transposed: [z][n][k]
__device__ __nv_bfloat16 g_Blo[(size_t)NZ * HH * HH];

// ================= PTX helpers =================
__device__ __forceinline__ uint32_t smem_u32(const void* p) {
    uint32_t a;
    asm("{ .reg .u64 t; cvta.to.shared.u64 t, %1; cvt.u32.u64 %0, t; }" : "=r"(a) : "l"(p));
    return a;
}
__device__ __forceinline__ void red4(float* p, float x, float y, float z, float w) {
    asm volatile("red.global.add.v4.f32 [%0], {%1,%2,%3,%4};"
                 :: "l"(p), "f"(x), "f"(y), "f"(z), "f"(w) : "memory");
}
__device__ __forceinline__ void ldsm4(uint32_t* r, uint32_t addr) {
    asm volatile("ldmatrix.sync.aligned.m8n8.x4.shared.b16 {%0,%1,%2,%3}, [%4];"
                 : "=r"(r[0]), "=r"(r[1]), "=r"(r[2]), "=r"(r[3]) : "r"(addr));
}
__device__ __forceinline__ void mma_bf16(float* d, const uint32_t* a, const uint32_t* b) {
    asm volatile(
        "mma.sync.aligned.m16n8k16.row.col.f32.bf16.bf16.f32 "
        "{%0,%1,%2,%3}, {%4,%5,%6,%7}, {%8,%9}, {%0,%1,%2,%3};"
        : "+f"(d[0]), "+f"(d[1]), "+f"(d[2]), "+f"(d[3])
        : "r"(a[0]), "r"(a[1]), "r"(a[2]), "r"(a[3]), "r"(b[0]), "r"(b[1]));
}
__device__ __forceinline__ void cp_async16(uint32_t saddr, const void* gaddr) {
    asm volatile("cp.async.cg.shared.global [%0], [%1], 16;" :: "r"(saddr), "l"(gaddr));
}
__device__ __forceinline__ void cp_async8(uint32_t saddr, const void* gaddr) {
    asm volatile("cp.async.ca.shared.global [%0], [%1], 8;" :: "r"(saddr), "l"(gaddr));
}
#define CP_COMMIT() asm volatile("cp.async.commit_group;" ::: "memory")
#define CP_WAIT(n)  asm volatile("cp.async.wait_group %0;" :: "n"(n) : "memory")

// ================= phase kernels =================
__global__ void zero_kernel() {
    size_t tid = (size_t)blockIdx.x * blockDim.x + threadIdx.x;
    size_t stride = (size_t)gridDim.x * blockDim.x;
    float4 z = make_float4(0.f, 0.f, 0.f, 0.f);
    float4* h4 = reinterpret_cast<float4*>(g_h);
    for (size_t i = tid; i < (size_t)NN * HH / 4; i += stride) h4[i] = z;
    float4* c4 = reinterpret_cast<float4*>(g_cnt);
    for (size_t i = tid; i < (size_t)NN * RR / 4; i += stride) c4[i] = z;
}

// counts + packed edge index
__global__ void count_kernel(const int* __restrict__ ei, const int* __restrict__ et) {
    int e = blockIdx.x * blockDim.x + threadIdx.x;
    if (e < EE) {
        int src = ei[e];
        int dst = ei[EE + e];
        int r = et[e];
        int seg = dst * RR + r;
        g_eidx[e] = make_int2(src, seg);
        atomicAdd(&g_cnt[seg], 1.0f);
    }
}

// layer 1 scatter: cp.async-staged, 8 edges per warp (one shot), 32KB/block
__global__ __launch_bounds__(256) void scatter1_kernel(const float* __restrict__ W1) {
    extern __shared__ char smem[];
    const int wid = threadIdx.x >> 5, lane = threadIdx.x & 31;
    char* buf = smem + wid * (8 * 512);
    const int e0 = (blockIdx.x * 8 + wid) * 8;

    int2 ev = g_eidx[e0 + (lane & 7)];
    float cw = (lane < 8) ? g_cnt[ev.y] : 1.0f;
    float winv = __frcp_rn(fmaxf(cw, 1.0f));

#pragma unroll
    for (int j = 0; j < 8; j++) {
        int srcj = __shfl_sync(0xffffffffu, ev.x, j);
        int segj = __shfl_sync(0xffffffffu, ev.y, j);
        const char* g = reinterpret_cast<const char*>(W1) +
                        ((size_t)(segj & 7) * NN + srcj) * (HH * 4) + lane * 16;
        cp_async16(smem_u32(buf + j * 512 + lane * 16), g);
    }
    CP_COMMIT();
    CP_WAIT(0);

#pragma unroll
    for (int j = 0; j < 8; j++) {
        int segj = __shfl_sync(0xffffffffu, ev.y, j);
        float wj = __shfl_sync(0xffffffffu, winv, j);
        float4 v = *reinterpret_cast<float4*>(buf + j * 512 + lane * 16);
        red4(g_h + (size_t)(segj >> 3) * HH + lane * 4,
             wj * v.x, wj * v.y, wj * v.z, wj * v.w);
    }
}

// fused: h = relu(g_h + root1 + b1) -> bf16 hi/lo split
__global__ void fin1prepA_kernel(const float* __restrict__ root1, const float* __restrict__ b1) {
    int i = blockIdx.x * blockDim.x + threadIdx.x;
    if (i >= NN * HH / 4) return;
    float4 h = reinterpret_cast<const float4*>(g_h)[i];
    float4 r = reinterpret_cast<const float4*>(root1)[i];
    float4 b = reinterpret_cast<const float4*>(b1)[i & (HH / 4 - 1)];
    float x = fmaxf(h.x + r.x + b.x, 0.f);
    float y = fmaxf(h.y + r.y + b.y, 0.f);
    float z = fmaxf(h.z + r.z + b.z, 0.f);
    float w = fmaxf(h.w + r.w + b.w, 0.f);
    __nv_bfloat16 hx = __float2bfloat16(x), hy = __float2bfloat16(y);
    __nv_bfloat16 hz = __float2bfloat16(z), hw = __float2bfloat16(w);
    __nv_bfloat16 lx = __float2bfloat16(x - __bfloat162float(hx));
    __nv_bfloat16 ly = __float2bfloat16(y - __bfloat162float(hy));
    __nv_bfloat16 lz = __float2bfloat16(z - __bfloat162float(hz));
    __nv_bfloat16 lw = __float2bfloat16(w - __bfloat162float(hw));
    __nv_bfloat162 h0 = __halves2bfloat162(hx, hy), h1 = __halves2bfloat162(hz, hw);
    __nv_bfloat162 l0 = __halves2bfloat162(lx, ly), l1 = __halves2bfloat162(lz, lw);
    uint2 ph, pl;
    ph.x = *reinterpret_cast<uint32_t*>(&h0); ph.y = *reinterpret_cast<uint32_t*>(&h1);
    pl.x = *reinterpret_cast<uint32_t*>(&l0); pl.y = *reinterpret_cast<uint32_t*>(&l1);
    reinterpret_cast<uint2*>(g_Ahi)[i] = ph;
    reinterpret_cast<uint2*>(g_Alo)[i] = pl;
}

// W2 / root2 -> transposed bf16 hi/lo:  B[z][n][k] = W[z][k][n]
__global__ void prepB_kernel(const float* __restrict__ W2, const float* __restrict__ root2) {
    int idx = blockIdx.x * blockDim.x + threadIdx.x;
    if (idx >= NZ * HH * HH) return;
    int z = idx >> 14;
    int n = (idx >> 7) & 127;
    int k = idx & 127;
    float v = (z < RR) ? W2[((size_t)z << 14) + k * HH + n] : root2[k * HH + n];
    __nv_bfloat16 hi = __float2bfloat16(v);
    __nv_bfloat16 lo = __float2bfloat16(v - __bfloat162float(hi));
    g_Bhi[idx] = hi;
    g_Blo[idx] = lo;
}

// ================= HMMA GEMM (double-buffered B via cp.async) =================
#define PITCH 136
#define PITCHB (PITCH * 2)
#define TILEB (128 * PITCHB)            // 34816 B
static constexpr int SM_AHI = 0;
static constexpr int SM_ALO = SM_AHI + TILEB;
static constexpr int SM_B0 = SM_ALO + TILEB;             // buf0: hi then lo
static constexpr int SM_B1 = SM_B0 + 2 * TILEB;          // buf1: hi then lo
static constexpr int SM_TOTAL = SM_B1 + 2 * TILEB;       // 208896 B

__device__ __forceinline__ void stage_B_async(char* smem, int buf_base, int z, int tid) {
#pragma unroll
    for (int i = 0; i < 8; i++) {
        int idx = tid + i * 256;
        int row = idx >> 4, seg = idx & 15;
        uint32_t so = row * PITCHB + seg * 16;
        const uint4* Bh = reinterpret_cast<const uint4*>(g_Bhi) + (size_t)z * 2048 + row * 16 + seg;
        const uint4* Bl = reinterpret_cast<const uint4*>(g_Blo) + (size_t)z * 2048 + row * 16 + seg;
        cp_async16(smem_u32(smem + buf_base + so), Bh);
        cp_async16(smem_u32(smem + buf_base + TILEB + so), Bl);
    }
}

__global__ __launch_bounds__(256, 1) void gemm_kernel(const float* __restrict__ b2) {
    extern __shared__ char smem[];
    uint32_t sb = smem_u32(smem);
    const int tid = threadIdx.x;
    const int wid = tid >> 5, lane = tid & 31;
    const int warp_m = (wid & 3) * 32;
    const int warp_n = (wid >> 2) * 64;
    const int row0 = blockIdx.x * 128;

    // prologue: async-stage B[0] into buf0
    stage_B_async(smem, SM_B0, 0, tid);
    CP_COMMIT();

    // ---- stage A hi/lo (once)
    {
        uint4 zz = make_uint4(0, 0, 0, 0);
#pragma unroll
        for (int i = 0; i < 8; i++) {
            int idx = tid + i * 256;
            int row = idx >> 4, seg = idx & 15;
            int gr = row0 + row;
            bool v = gr < NN;
            uint32_t so = row * PITCHB + seg * 16;
            const uint4* Ah = reinterpret_cast<const uint4*>(g_Ahi) + (size_t)gr * 16 + seg;
            const uint4* Al = reinterpret_cast<const uint4*>(g_Alo) + (size_t)gr * 16 + seg;
            *reinterpret_cast<uint4*>(smem + SM_AHI + so) = v ? *Ah : zz;
            *reinterpret_cast<uint4*>(smem + SM_ALO + so) = v ? *Al : zz;
        }
    }

    const uint32_t a_row = (uint32_t)(warp_m + (lane & 15));
    const uint32_t a_base = a_row * PITCHB + ((lane >> 4) << 3) * 2;
    const uint32_t b_n = (uint32_t)(warp_n + (lane & 7) + ((lane >> 4) << 3));
    const uint32_t b_base = b_n * PITCHB + (((lane >> 3) & 1) << 3) * 2;

    for (int z = 0; z < NZ; z++) {
        const int cur = (z & 1) ? SM_B1 : SM_B0;
        if (z + 1 < NZ) {
            stage_B_async(smem, (z & 1) ? SM_B0 : SM_B1, z + 1, tid);
            CP_COMMIT();
            CP_WAIT(1);
        } else {
            CP_WAIT(0);
        }
        __syncthreads();

        float acc[16][4];
#pragma unroll
        for (int i = 0; i < 16; i++)
#pragma unroll
            for (int j = 0; j < 4; j++) acc[i][j] = 0.f;

#pragma unroll
        for (int k = 0; k < 8; k++) {
            const uint32_t koff = (uint32_t)(k * 32);
            uint32_t ahi[2][4], alo[2][4];
#pragma unroll
            for (int mt = 0; mt < 2; mt++) {
                uint32_t ao = a_base + (uint32_t)(mt * 16) * PITCHB + koff;
                ldsm4(ahi[mt], sb + SM_AHI + ao);
                ldsm4(alo[mt], sb + SM_ALO + ao);
            }
            uint32_t bhi[8][2], blo[8][2];
#pragma unroll
            for (int ntp = 0; ntp < 4; ntp++) {
                uint32_t bo = b_base + (uint32_t)(ntp * 16) * PITCHB + koff;
                uint32_t rh[4], rl[4];
                ldsm4(rh, sb + cur + bo);
                ldsm4(rl, sb + cur + TILEB + bo);
                bhi[ntp * 2][0] = rh[0]; bhi[ntp * 2][1] = rh[1];
                bhi[ntp * 2 + 1][0] = rh[2]; bhi[ntp * 2 + 1][1] = rh[3];
                blo[ntp * 2][0] = rl[0]; blo[ntp * 2][1] = rl[1];
                blo[ntp * 2 + 1][0] = rl[2]; blo[ntp * 2 + 1][1] = rl[3];
            }
#pragma unroll
            for (int mt = 0; mt < 2; mt++)
#pragma unroll
                for (int nt = 0; nt < 8; nt++) {
                    mma_bf16(acc[mt * 8 + nt], ahi[mt], bhi[nt]);
                    mma_bf16(acc[mt * 8 + nt], ahi[mt], blo[nt]);
                    mma_bf16(acc[mt * 8 + nt], alo[mt], bhi[nt]);
                }
        }

        // ---- epilogue
        const int erow = lane >> 2;
        const int ecol0 = (lane & 3) * 2;
        if (z < RR) {
            __half* out = g_xr + (size_t)z * NN * HH;
#pragma unroll
            for (int mt = 0; mt < 2; mt++) {
                int r0 = row0 + warp_m + mt * 16 + erow;
                int r1 = r0 + 8;
                bool v0 = r0 < NN, v1 = r1 < NN;
#pragma unroll
                for (int nt = 0; nt < 8; nt++) {
                    int c = warp_n + nt * 8 + ecol0;
                    float* a4 = acc[mt * 8 + nt];
                    if (v0) {
                        __half2 o = __floats2half2_rn(a4[0], a4[1]);
                        *reinterpret_cast<__half2*>(out + (size_t)r0 * HH + c) = o;
                    }
                    if (v1) {
                        __half2 o = __floats2half2_rn(a4[2], a4[3]);
                        *reinterpret_cast<__half2*>(out + (size_t)r1 * HH + c) = o;
                    }
                }
            }
        } else {
            float* out = g_h2;
#pragma unroll
            for (int mt = 0; mt < 2; mt++) {
                int r0 = row0 + warp_m + mt * 16 + erow;
                int r1 = r0 + 8;
                bool v0 = r0 < NN, v1 = r1 < NN;
#pragma unroll
                for (int nt = 0; nt < 8; nt++) {
                    int c = warp_n + nt * 8 + ecol0;
                    float bb0 = b2[c], bb1 = b2[c + 1];
                    float* a4 = acc[mt * 8 + nt];
                    if (v0) {
                        float2 o = make_float2(a4[0] + bb0, a4[1] + bb1);
                        *reinterpret_cast<float2*>(out + (size_t)r0 * HH + c) = o;
                    }
                    if (v1) {
                        float2 o = make_float2(a4[2] + bb0, a4[3] + bb1);
                        *reinterpret_cast<float2*>(out + (size_t)r1 * HH + c) = o;
                    }
                }
            }
        }
        __syncthreads();   // all reads of cur done before it is overwritten
    }
}

// layer 2 scatter: cp.async-staged fp16 rows, 8 edges per warp, 16KB/block
__global__ __launch_bounds__(256) void scatter2_kernel() {
    extern __shared__ char smem[];
    const int wid = threadIdx.x >> 5, lane = threadIdx.x & 31;
    char* buf = smem + wid * (8 * 256);
    const int e0 = (blockIdx.x * 8 + wid) * 8;

    int2 ev = g_eidx[e0 + (lane & 7)];
    float cw = (lane < 8) ? g_cnt[ev.y] : 1.0f;
    float winv = __frcp_rn(fmaxf(cw, 1.0f));

#pragma unroll
    for (int j = 0; j < 8; j++) {
        int srcj = __shfl_sync(0xffffffffu, ev.x, j);
        int segj = __shfl_sync(0xffffffffu, ev.y, j);
        const char* g = reinterpret_cast<const char*>(g_xr) +
                        ((size_t)(segj & 7) * NN + srcj) * (HH * 2) + lane * 8;
        cp_async8(smem_u32(buf + j * 256 + lane * 8), g);
    }
    CP_COMMIT();
    CP_WAIT(0);

#pragma unroll
    for (int j = 0; j < 8; j++) {
        int segj = __shfl_sync(0xffffffffu, ev.y, j);
        float wj = __shfl_sync(0xffffffffu, winv, j);
        uint2 p = *reinterpret_cast<uint2*>(buf + j * 256 + lane * 8);
        __half2 h0 = *reinterpret_cast<__half2*>(&p.x);
        __half2 h1 = *reinterpret_cast<__half2*>(&p.y);
        float2 f0 = __half22float2(h0);
        float2 f1 = __half22float2(h1);
        red4(g_h2 + (size_t)(segj >> 3) * HH + lane * 4,
             wj * f0.x, wj * f0.y, wj * f1.x, wj * f1.y);
    }
}

// out = relu(h2) @ lin_w + lin_b
__global__ void final_kernel(const float* __restrict__ lin_w, const float* __restrict__ lin_b,
                             float* __restrict__ out) {
    __shared__ float sw[HH * CC];
    __shared__ float sh[32][HH + 1];
    int tid = threadIdx.x;
    for (int i = tid; i < HH * CC; i += 256) sw[i] = lin_w[i];
    int n0 = blockIdx.x * 32;
    for (int i = tid; i < 32 * HH; i += 256) {
        int nl = i / HH, k = i % HH;
        int n = n0 + nl;
        sh[nl][k] = (n < NN) ? fmaxf(g_h2[(size_t)n * HH + k], 0.f) : 0.f;
    }
    __syncthreads();
#pragma unroll
    for (int j = 0; j < 5; j++) {
        int idx = tid + j * 256;
        int nl = idx / CC, c = idx % CC;
        float acc = lin_b[c];
#pragma unroll
        for (int k = 0; k < HH; k++) acc = fmaf(sh[nl][k], sw[k * CC + c], acc);
        int n = n0 + nl;
        if (n < NN) out[(size_t)n * CC + c] = acc;
    }
}

// ================= launch =================
extern "C" void kernel_launch(void* const* d_in, const int* in_sizes, int n_in,
                              void* d_out, int out_size) {
    const int* ei = (const int*)d_in[0];
    const int* et = (const int*)d_in[1];
    const float* W1 = (const float*)d_in[2];
    const float* root1 = (const float*)d_in[3];
    const float* b1 = (const float*)d_in[4];
    const float* W2 = (const float*)d_in[5];
    const float* root2 = (const float*)d_in[6];
    const float* b2 = (const float*)d_in[7];
    const float* lin_w = (const float*)d_in[8];
    const float* lin_b = (const float*)d_in[9];
    float* out = (float*)d_out;

    cudaFuncSetAttribute(gemm_kernel, cudaFuncAttributeMaxDynamicSharedMemorySize, SM_TOTAL);

    zero_kernel<<<2048, 256>>>();
    prepB_kernel<<<(NZ * HH * HH + 255) / 256, 256>>>(W2, root2);
    count_kernel<<<(EE + 255) / 256, 256>>>(ei, et);
    scatter1_kernel<<<EE / 64, 256, 32768>>>(W1);      // 8 edges/warp, 8 warps/block
    fin1prepA_kernel<<<(NN * HH / 4 + 255) / 256, 256>>>(root1, b1);
    gemm_kernel<<<MTILES, 256, SM_TOTAL>>>(b2);
    scatter2_kernel<<<EE / 64, 256, 16384>>>();        // 8 edges/warp, 8 warps/block
    final_kernel<<<(NN + 31) / 32, 256>>>(lin_w, lin_b, out);
}

// round 14
// speedup vs baseline: 1.8444x; 1.2024x over previous
#include <cuda_runtime.h>
#include <cuda_bf16.h>
#include <cuda_fp16.h>
#include <cstdint>

#define NN 50000
#define RR 8
#define HH 128
#define CC 40
#define EE 800000
#define MTILES 391     // ceil(NN/128)

// ---- scratch (device globals; no allocation allowed) ----
__device__ float g_cnt[NN * RR];                       // raw counts
__device__ int2 g_eidx[EE];                            // packed {src, dst*8+rel}
__device__ float g_h[(size_t)NN * HH];                 // layer-1 fp32 accumulator
__device__ __half g_h16[(size_t)NN * HH];              // h in fp16 (L2-resident gather table)
__device__ __half g_agg[(size_t)RR * NN * HH];         // 102.4 MB: per-rel weighted sums (f16)
__device__ float g_h2[(size_t)NN * HH];
__device__ __nv_bfloat16 g_Ahi[(size_t)NN * HH];
__device__ __nv_bfloat16 g_Alo[(size_t)NN * HH];
__device__ __half g_Bf16[(size_t)RR * HH * HH];        // W2 transposed [z][n][k] f16
__device__ __nv_bfloat16 g_Brh[HH * HH];               // root2 transposed hi
__device__ __nv_bfloat16 g_Brl[HH * HH];               // root2 transposed lo

// ================= PTX helpers =================
__device__ __forceinline__ uint32_t smem_u32(const void* p) {
    uint32_t a;
    asm("{ .reg .u64 t; cvta.to.shared.u64 t, %1; cvt.u32.u64 %0, t; }" : "=r"(a) : "l"(p));
    return a;
}
__device__ __forceinline__ void red4(float* p, float x, float y, float z, float w) {
    asm volatile("red.global.add.v4.f32 [%0], {%1,%2,%3,%4};"
                 :: "l"(p), "f"(x), "f"(y), "f"(z), "f"(w) : "memory");
}
__device__ __forceinline__ void red4_h2(void* p, uint32_t a, uint32_t b, uint32_t c, uint32_t d) {
    asm volatile("red.global.add.noftz.v4.f16x2 [%0], {%1,%2,%3,%4};"
                 :: "l"(p), "r"(a), "r"(b), "r"(c), "r"(d) : "memory");
}
__device__ __forceinline__ void ldsm4(uint32_t* r, uint32_t addr) {
    asm volatile("ldmatrix.sync.aligned.m8n8.x4.shared.b16 {%0,%1,%2,%3}, [%4];"
                 : "=r"(r[0]), "=r"(r[1]), "=r"(r[2]), "=r"(r[3]) : "r"(addr));
}
__device__ __forceinline__ void mma_bf16(float* d, const uint32_t* a, const uint32_t* b) {
    asm volatile(
        "mma.sync.aligned.m16n8k16.row.col.f32.bf16.bf16.f32 "
        "{%0,%1,%2,%3}, {%4,%5,%6,%7}, {%8,%9}, {%0,%1,%2,%3};"
        : "+f"(d[0]), "+f"(d[1]), "+f"(d[2]), "+f"(d[3])
        : "r"(a[0]), "r"(a[1]), "r"(a[2]), "r"(a[3]), "r"(b[0]), "r"(b[1]));
}
__device__ __forceinline__ void mma_f16(float* d, const uint32_t* a, const uint32_t* b) {
    asm volatile(
        "mma.sync.aligned.m16n8k16.row.col.f32.f16.f16.f32 "
        "{%0,%1,%2,%3}, {%4,%5,%6,%7}, {%8,%9}, {%0,%1,%2,%3};"
        : "+f"(d[0]), "+f"(d[1]), "+f"(d[2]), "+f"(d[3])
        : "r"(a[0]), "r"(a[1]), "r"(a[2]), "r"(a[3]), "r"(b[0]), "r"(b[1]));
}
__device__ __forceinline__ void cp_async16(uint32_t saddr, const void* gaddr) {
    asm volatile("cp.async.cg.shared.global [%0], [%1], 16;" :: "r"(saddr), "l"(gaddr));
}
#define CP_COMMIT() asm volatile("cp.async.commit_group;" ::: "memory")
#define CP_WAIT(n)  asm volatile("cp.async.wait_group %0;" :: "n"(n) : "memory")

// ================= phase kernels =================
__global__ void zero_kernel() {
    size_t tid = (size_t)blockIdx.x * blockDim.x + threadIdx.x;
    size_t stride = (size_t)gridDim.x * blockDim.x;
    float4 z = make_float4(0.f, 0.f, 0.f, 0.f);
    float4* h4 = reinterpret_cast<float4*>(g_h);
    for (size_t i = tid; i < (size_t)NN * HH / 4; i += stride) h4[i] = z;
    float4* c4 = reinterpret_cast<float4*>(g_cnt);
    for (size_t i = tid; i < (size_t)NN * RR / 4; i += stride) c4[i] = z;
    float4* a4 = reinterpret_cast<float4*>(g_agg);
    for (size_t i = tid; i < (size_t)RR * NN * HH / 8; i += stride) a4[i] = z;
}

// counts + packed edge index
__global__ void count_kernel(const int* __restrict__ ei, const int* __restrict__ et) {
    int e = blockIdx.x * blockDim.x + threadIdx.x;
    if (e < EE) {
        int src = ei[e];
        int dst = ei[EE + e];
        int r = et[e];
        int seg = dst * RR + r;
        g_eidx[e] = make_int2(src, seg);
        atomicAdd(&g_cnt[seg], 1.0f);
    }
}

// layer 1 scatter: cp.async-staged, 8 edges per warp (unchanged from R13)
__global__ __launch_bounds__(256) void scatter1_kernel(const float* __restrict__ W1) {
    extern __shared__ char smem[];
    const int wid = threadIdx.x >> 5, lane = threadIdx.x & 31;
    char* buf = smem + wid * (8 * 512);
    const int e0 = (blockIdx.x * 8 + wid) * 8;

    int2 ev = g_eidx[e0 + (lane & 7)];
    float cw = (lane < 8) ? g_cnt[ev.y] : 1.0f;
    float winv = __frcp_rn(fmaxf(cw, 1.0f));

#pragma unroll
    for (int j = 0; j < 8; j++) {
        int srcj = __shfl_sync(0xffffffffu, ev.x, j);
        int segj = __shfl_sync(0xffffffffu, ev.y, j);
        const char* g = reinterpret_cast<const char*>(W1) +
                        ((size_t)(segj & 7) * NN + srcj) * (HH * 4) + lane * 16;
        cp_async16(smem_u32(buf + j * 512 + lane * 16), g);
    }
    CP_COMMIT();
    CP_WAIT(0);

#pragma unroll
    for (int j = 0; j < 8; j++) {
        int segj = __shfl_sync(0xffffffffu, ev.y, j);
        float wj = __shfl_sync(0xffffffffu, winv, j);
        float4 v = *reinterpret_cast<float4*>(buf + j * 512 + lane * 16);
        red4(g_h + (size_t)(segj >> 3) * HH + lane * 4,
             wj * v.x, wj * v.y, wj * v.z, wj * v.w);
    }
}

// fused: h = relu(g_h + root1 + b1) -> bf16 hi/lo split + fp16 copy
__global__ void fin1prepA_kernel(const float* __restrict__ root1, const float* __restrict__ b1) {
    int i = blockIdx.x * blockDim.x + threadIdx.x;
    if (i >= NN * HH / 4) return;
    float4 h = reinterpret_cast<const float4*>(g_h)[i];
    float4 r = reinterpret_cast<const float4*>(root1)[i];
    float4 b = reinterpret_cast<const float4*>(b1)[i & (HH / 4 - 1)];
    float x = fmaxf(h.x + r.x + b.x, 0.f);
    float y = fmaxf(h.y + r.y + b.y, 0.f);
    float z = fmaxf(h.z + r.z + b.z, 0.f);
    float w = fmaxf(h.w + r.w + b.w, 0.f);
    __nv_bfloat16 hx = __float2bfloat16(x), hy = __float2bfloat16(y);
    __nv_bfloat16 hz = __float2bfloat16(z), hw = __float2bfloat16(w);
    __nv_bfloat16 lx = __float2bfloat16(x - __bfloat162float(hx));
    __nv_bfloat16 ly = __float2bfloat16(y - __bfloat162float(hy));
    __nv_bfloat16 lz = __float2bfloat16(z - __bfloat162float(hz));
    __nv_bfloat16 lw = __float2bfloat16(w - __bfloat162float(hw));
    __nv_bfloat162 h0 = __halves2bfloat162(hx, hy), h1 = __halves2bfloat162(hz, hw);
    __nv_bfloat162 l0 = __halves2bfloat162(lx, ly), l1 = __halves2bfloat162(lz, lw);
    uint2 ph, pl;
    ph.x = *reinterpret_cast<uint32_t*>(&h0); ph.y = *reinterpret_cast<uint32_t*>(&h1);
    pl.x = *reinterpret_cast<uint32_t*>(&l0); pl.y = *reinterpret_cast<uint32_t*>(&l1);
    reinterpret_cast<uint2*>(g_Ahi)[i] = ph;
    reinterpret_cast<uint2*>(g_Alo)[i] = pl;
    __half2 f0 = __floats2half2_rn(x, y), f1 = __floats2half2_rn(z, w);
    uint2 pf;
    pf.x = *reinterpret_cast<uint32_t*>(&f0); pf.y = *reinterpret_cast<uint32_t*>(&f1);
    reinterpret_cast<uint2*>(g_h16)[i] = pf;
}

// W2 -> transposed f16 [z][n][k]; root2 -> transposed bf16 hi/lo
__global__ void prepB_kernel(const float* __restrict__ W2, const float* __restrict__ root2) {
    int idx = blockIdx.x * blockDim.x + threadIdx.x;
    if (idx >= 9 * HH * HH) return;
    int z = idx >> 14;
    int n = (idx >> 7) & 127;
    int k = idx & 127;
    if (z < RR) {
        float v = W2[((size_t)z << 14) + k * HH + n];
        g_Bf16[idx] = __float2half(v);
    } else {
        float v = root2[k * HH + n];
        __nv_bfloat16 hi = __float2bfloat16(v);
        g_Brh[n * HH + k] = hi;
        g_Brl[n * HH + k] = __float2bfloat16(v - __bfloat162float(hi));
    }
}

// layer 2 aggregate: agg[rel][dst] += w * h16[src]   (gathers L2-resident)
// 16 edges per warp; lanes split: half = lane>>4 picks edge parity, q = lane&15 picks 16B chunk
__global__ __launch_bounds__(256) void scatter2_kernel() {
    const int wid = threadIdx.x >> 5, lane = threadIdx.x & 31;
    const int e0 = (blockIdx.x * 8 + wid) * 16;
    int2 ev = g_eidx[e0 + (lane & 15)];
    float cw = g_cnt[ev.y];
    float winv = __frcp_rn(fmaxf(cw, 1.0f));
    __half2 wh2 = __floats2half2_rn(winv, winv);
    uint32_t wbits_own = *reinterpret_cast<uint32_t*>(&wh2);

    const int half_ = lane >> 4;
    const int q = lane & 15;

    int srcj[8], segj[8];
    uint32_t wb[8];
#pragma unroll
    for (int t = 0; t < 8; t++) {
        int esel = 2 * t + half_;
        srcj[t] = __shfl_sync(0xffffffffu, ev.x, esel);
        segj[t] = __shfl_sync(0xffffffffu, ev.y, esel);
        wb[t] = __shfl_sync(0xffffffffu, wbits_own, esel);
    }
    uint4 p[8];
#pragma unroll
    for (int t = 0; t < 8; t++)
        p[t] = __ldg(reinterpret_cast<const uint4*>(g_h16 + (size_t)srcj[t] * HH) + q);
#pragma unroll
    for (int t = 0; t < 8; t++) {
        __half2 w2 = *reinterpret_cast<__half2*>(&wb[t]);
        __half2 a = __hmul2(*reinterpret_cast<__half2*>(&p[t].x), w2);
        __half2 b = __hmul2(*reinterpret_cast<__half2*>(&p[t].y), w2);
        __half2 c = __hmul2(*reinterpret_cast<__half2*>(&p[t].z), w2);
        __half2 d = __hmul2(*reinterpret_cast<__half2*>(&p[t].w), w2);
        __half* dst = g_agg + ((size_t)(segj[t] & 7) * NN + (segj[t] >> 3)) * HH + q * 8;
        red4_h2(dst, *reinterpret_cast<uint32_t*>(&a), *reinterpret_cast<uint32_t*>(&b),
                *reinterpret_cast<uint32_t*>(&c), *reinterpret_cast<uint32_t*>(&d));
    }
}

// ================= HMMA GEMM: h2 = sum_r agg_r @ W2_r + h @ root2 + b2 =================
// persistent accumulators across all 9 passes; single epilogue.
#define PITCH 136
#define PITCHB (PITCH * 2)
#define TILEB (128 * PITCHB)            // 34816 B
static constexpr int SM_RH = 0;                          // root A hi (bf16)
static constexpr int SM_RL = TILEB;                      // root A lo
static constexpr int SM_T0 = 2 * TILEB;                  // pair0 A / root B hi
static constexpr int SM_T1 = 3 * TILEB;                  // pair0 B / root B lo
static constexpr int SM_T2 = 4 * TILEB;                  // pair1 A
static constexpr int SM_T3 = 5 * TILEB;                  // pair1 B
static constexpr int SM_TOTAL = 6 * TILEB;               // 208896 B

__device__ __forceinline__ void stage_agg(char* smem, int bufA, int bufB, int z,
                                          int row0, int tid) {
#pragma unroll
    for (int i = 0; i < 8; i++) {
        int idx = tid + i * 256;
        int row = idx >> 4, seg = idx & 15;
        int gr = row0 + row; if (gr >= NN) gr = NN - 1;
        const char* srcA = reinterpret_cast<const char*>(g_agg) +
                           ((size_t)z * NN + gr) * (HH * 2) + seg * 16;
        cp_async16(smem_u32(smem + bufA + row * PITCHB + seg * 16), srcA);
        const char* srcB = reinterpret_cast<const char*>(g_Bf16) +
                           (size_t)z * (HH * HH * 2) + row * (HH * 2) + seg * 16;
        cp_async16(smem_u32(smem + bufB + row * PITCHB + seg * 16), srcB);
    }
}

__global__ __launch_bounds__(256, 1) void gemm_kernel(const float* __restrict__ b2) {
    extern __shared__ char smem[];
    uint32_t sb = smem_u32(smem);
    const int tid = threadIdx.x;
    const int wid = tid >> 5, lane = tid & 31;
    const int warp_m = (wid & 3) * 32;
    const int warp_n = (wid >> 2) * 64;
    const int row0 = blockIdx.x * 128;

    // group 0: root A (bf16 hi/lo)
#pragma unroll
    for (int i = 0; i < 8; i++) {
        int idx = tid + i * 256;
        int row = idx >> 4, seg = idx & 15;
        int gr = row0 + row; if (gr >= NN) gr = NN - 1;
        const char* Ah = reinterpret_cast<const char*>(g_Ahi) + (size_t)gr * (HH * 2) + seg * 16;
        const char* Al = reinterpret_cast<const char*>(g_Alo) + (size_t)gr * (HH * 2) + seg * 16;
        cp_async16(smem_u32(smem + SM_RH + row * PITCHB + seg * 16), Ah);
        cp_async16(smem_u32(smem + SM_RL + row * PITCHB + seg * 16), Al);
    }
    CP_COMMIT();
    // group 1: z=0 tiles into pair0
    stage_agg(smem, SM_T0, SM_T1, 0, row0, tid);
    CP_COMMIT();

    const uint32_t a_row = (uint32_t)(warp_m + (lane & 15));
    const uint32_t a_base = a_row * PITCHB + ((lane >> 4) << 3) * 2;
    const uint32_t b_n = (uint32_t)(warp_n + (lane & 7) + ((lane >> 4) << 3));
    const uint32_t b_base = b_n * PITCHB + (((lane >> 3) & 1) << 3) * 2;

    float acc[16][4];
#pragma unroll
    for (int i = 0; i < 16; i++)
#pragma unroll
        for (int j = 0; j < 4; j++) acc[i][j] = 0.f;

    // ---- 8 agg passes (f16 x f16) ----
    for (int z = 0; z < RR; z++) {
        const int curA = (z & 1) ? SM_T2 : SM_T0;
        const int curB = (z & 1) ? SM_T3 : SM_T1;
        if (z < RR - 1) {
            stage_agg(smem, (z & 1) ? SM_T0 : SM_T2, (z & 1) ? SM_T1 : SM_T3, z + 1, row0, tid);
            CP_COMMIT();
        } else {
            // stage root B hi/lo into pair0 (T0, T1)
#pragma unroll
            for (int i = 0; i < 8; i++) {
                int idx = tid + i * 256;
                int row = idx >> 4, seg = idx & 15;
                const char* Bh = reinterpret_cast<const char*>(g_Brh) + row * (HH * 2) + seg * 16;
                const char* Bl = reinterpret_cast<const char*>(g_Brl) + row * (HH * 2) + seg * 16;
                cp_async16(smem_u32(smem + SM_T0 + row * PITCHB + seg * 16), Bh);
                cp_async16(smem_u32(smem + SM_T1 + row * PITCHB + seg * 16), Bl);
            }
            CP_COMMIT();
        }
        CP_WAIT(1);
        __syncthreads();

#pragma unroll
        for (int k = 0; k < 8; k++) {
            const uint32_t koff = (uint32_t)(k * 32);
            uint32_t af[2][4];
#pragma unroll
            for (int mt = 0; mt < 2; mt++)
                ldsm4(af[mt], sb + curA + a_base + (uint32_t)(mt * 16) * PITCHB + koff);
            uint32_t bf[8][2];
#pragma unroll
            for (int ntp = 0; ntp < 4; ntp++) {
                uint32_t rh[4];
                ldsm4(rh, sb + curB + b_base + (uint32_t)(ntp * 16) * PITCHB + koff);
                bf[ntp * 2][0] = rh[0]; bf[ntp * 2][1] = rh[1];
                bf[ntp * 2 + 1][0] = rh[2]; bf[ntp * 2 + 1][1] = rh[3];
            }
#pragma unroll
            for (int mt = 0; mt < 2; mt++)
#pragma unroll
                for (int nt = 0; nt < 8; nt++)
                    mma_f16(acc[mt * 8 + nt], af[mt], bf[nt]);
        }
        __syncthreads();
    }

    // ---- root pass: 3 bf16 passes (hi*hi, lo*hi, hi*lo) ----
    CP_WAIT(0);
    __syncthreads();
#pragma unroll
    for (int p = 0; p < 3; p++) {
        const int aT = (p == 1) ? SM_RL : SM_RH;
        const int bT = (p == 2) ? SM_T1 : SM_T0;
#pragma unroll
        for (int k = 0; k < 8; k++) {
            const uint32_t koff = (uint32_t)(k * 32);
            uint32_t af[2][4];
#pragma unroll
            for (int mt = 0; mt < 2; mt++)
                ldsm4(af[mt], sb + aT + a_base + (uint32_t)(mt * 16) * PITCHB + koff);
            uint32_t bf[8][2];
#pragma unroll
            for (int ntp = 0; ntp < 4; ntp++) {
                uint32_t rh[4];
                ldsm4(rh, sb + bT + b_base + (uint32_t)(ntp * 16) * PITCHB + koff);
                bf[ntp * 2][0] = rh[0]; bf[ntp * 2][1] = rh[1];
                bf[ntp * 2 + 1][0] = rh[2]; bf[ntp * 2 + 1][1] = rh[3];
            }
#pragma unroll
            for (int mt = 0; mt < 2; mt++)
#pragma unroll
                for (int nt = 0; nt < 8; nt++)
                    mma_bf16(acc[mt * 8 + nt], af[mt], bf[nt]);
        }
    }

    // ---- single epilogue: h2 = acc + b2 ----
    const int erow = lane >> 2;
    const int ecol0 = (lane & 3) * 2;
#pragma unroll
    for (int mt = 0; mt < 2; mt++) {
        int r0 = row0 + warp_m + mt * 16 + erow;
        int r1 = r0 + 8;
        bool v0 = r0 < NN, v1 = r1 < NN;
#pragma unroll
        for (int nt = 0; nt < 8; nt++) {
            int c = warp_n + nt * 8 + ecol0;
            float bb0 = b2[c], bb1 = b2[c + 1];
            float* a4 = acc[mt * 8 + nt];
            if (v0) {
                float2 o = make_float2(a4[0] + bb0, a4[1] + bb1);
                *reinterpret_cast<float2*>(g_h2 + (size_t)r0 * HH + c) = o;
            }
            if (v1) {
                float2 o = make_float2(a4[2] + bb0, a4[3] + bb1);
                *reinterpret_cast<float2*>(g_h2 + (size_t)r1 * HH + c) = o;
            }
        }
    }
}

// out = relu(h2) @ lin_w + lin_b
__global__ void final_kernel(const float* __restrict__ lin_w, const float* __restrict__ lin_b,
                             float* __restrict__ out) {
    __shared__ float sw[HH * CC];
    __shared__ float sh[32][HH + 1];
    int tid = threadIdx.x;
    for (int i = tid; i < HH * CC; i += 256) sw[i] = lin_w[i];
    int n0 = blockIdx.x * 32;
    for (int i = tid; i < 32 * HH; i += 256) {
        int nl = i / HH, k = i % HH;
        int n = n0 + nl;
        sh[nl][k] = (n < NN) ? fmaxf(g_h2[(size_t)n * HH + k], 0.f) : 0.f;
    }
    __syncthreads();
#pragma unroll
    for (int j = 0; j < 5; j++) {
        int idx = tid + j * 256;
        int nl = idx / CC, c = idx % CC;
        float acc = lin_b[c];
#pragma unroll
        for (int k = 0; k < HH; k++) acc = fmaf(sh[nl][k], sw[k * CC + c], acc);
        int n = n0 + nl;
        if (n < NN) out[(size_t)n * CC + c] = acc;
    }
}

// ================= launch =================
extern "C" void kernel_launch(void* const* d_in, const int* in_sizes, int n_in,
                              void* d_out, int out_size) {
    const int* ei = (const int*)d_in[0];
    const int* et = (const int*)d_in[1];
    const float* W1 = (const float*)d_in[2];
    const float* root1 = (const float*)d_in[3];
    const float* b1 = (const float*)d_in[4];
    const float* W2 = (const float*)d_in[5];
    const float* root2 = (const float*)d_in[6];
    const float* b2 = (const float*)d_in[7];
    const float* lin_w = (const float*)d_in[8];
    const float* lin_b = (const float*)d_in[9];
    float* out = (float*)d_out;

    cudaFuncSetAttribute(gemm_kernel, cudaFuncAttributeMaxDynamicSharedMemorySize, SM_TOTAL);

    zero_kernel<<<4096, 256>>>();
    prepB_kernel<<<(9 * HH * HH + 255) / 256, 256>>>(W2, root2);
    count_kernel<<<(EE + 255) / 256, 256>>>(ei, et);
    scatter1_kernel<<<EE / 64, 256, 32768>>>(W1);      // 8 edges/warp
    fin1prepA_kernel<<<(NN * HH / 4 + 255) / 256, 256>>>(root1, b1);
    scatter2_kernel<<<EE / 128, 256>>>();              // 16 edges/warp, agg f16
    gemm_kernel<<<MTILES, 256, SM_TOTAL>>>(b2);
    final_kernel<<<(NN + 31) / 32, 256>>>(lin_w, lin_b, out);
}

// round 16
// speedup vs baseline: 1.8797x; 1.0191x over previous
#include <cuda_runtime.h>
#include <cuda_bf16.h>
#include <cuda_fp16.h>
#include <cstdint>

#define NN 50000
#define RR 8
#define HH 128
#define CC 40
#define EE 800000
#define MTILES 391     // ceil(NN/128)

// ---- scratch (device globals; no allocation allowed) ----
__device__ float g_cnt[NN * RR];                       // raw counts
__device__ int2 g_eidx[EE];                            // packed {src, dst*8+rel}
__device__ float g_h[(size_t)NN * HH];                 // layer-1 fp32 accumulator
__device__ __half g_h16[(size_t)NN * HH];              // h in fp16 (L2-resident gather table)
__device__ __half g_agg[(size_t)RR * NN * HH];         // 102.4 MB: per-rel weighted sums (f16)
__device__ float g_h2[(size_t)NN * HH];
__device__ __nv_bfloat16 g_Ahi[(size_t)NN * HH];
__device__ __nv_bfloat16 g_Alo[(size_t)NN * HH];
__device__ __half g_Bf16[(size_t)RR * HH * HH];        // W2 transposed [z][n][k] f16
__device__ __nv_bfloat16 g_Brh[HH * HH];               // root2 transposed hi
__device__ __nv_bfloat16 g_Brl[HH * HH];               // root2 transposed lo

// ================= PTX helpers =================
__device__ __forceinline__ uint32_t smem_u32(const void* p) {
    uint32_t a;
    asm("{ .reg .u64 t; cvta.to.shared.u64 t, %1; cvt.u32.u64 %0, t; }" : "=r"(a) : "l"(p));
    return a;
}
__device__ __forceinline__ void red4(float* p, float x, float y, float z, float w) {
    asm volatile("red.global.add.v4.f32 [%0], {%1,%2,%3,%4};"
                 :: "l"(p), "f"(x), "f"(y), "f"(z), "f"(w) : "memory");
}
__device__ __forceinline__ void red4_h2(void* p, uint32_t a, uint32_t b, uint32_t c, uint32_t d) {
    asm volatile("red.global.add.noftz.v4.f16x2 [%0], {%1,%2,%3,%4};"
                 :: "l"(p), "r"(a), "r"(b), "r"(c), "r"(d) : "memory");
}
__device__ __forceinline__ void ldsm4(uint32_t* r, uint32_t addr) {
    asm volatile("ldmatrix.sync.aligned.m8n8.x4.shared.b16 {%0,%1,%2,%3}, [%4];"
                 : "=r"(r[0]), "=r"(r[1]), "=r"(r[2]), "=r"(r[3]) : "r"(addr));
}
__device__ __forceinline__ void mma_bf16(float* d, const uint32_t* a, const uint32_t* b) {
    asm volatile(
        "mma.sync.aligned.m16n8k16.row.col.f32.bf16.bf16.f32 "
        "{%0,%1,%2,%3}, {%4,%5,%6,%7}, {%8,%9}, {%0,%1,%2,%3};"
        : "+f"(d[0]), "+f"(d[1]), "+f"(d[2]), "+f"(d[3])
        : "r"(a[0]), "r"(a[1]), "r"(a[2]), "r"(a[3]), "r"(b[0]), "r"(b[1]));
}
__device__ __forceinline__ void mma_f16(float* d, const uint32_t* a, const uint32_t* b) {
    asm volatile(
        "mma.sync.aligned.m16n8k16.row.col.f32.f16.f16.f32 "
        "{%0,%1,%2,%3}, {%4,%5,%6,%7}, {%8,%9}, {%0,%1,%2,%3};"
        : "+f"(d[0]), "+f"(d[1]), "+f"(d[2]), "+f"(d[3])
        : "r"(a[0]), "r"(a[1]), "r"(a[2]), "r"(a[3]), "r"(b[0]), "r"(b[1]));
}
__device__ __forceinline__ void cp_async16(uint32_t saddr, const void* gaddr) {
    asm volatile("cp.async.cg.shared.global [%0], [%1], 16;" :: "r"(saddr), "l"(gaddr));
}
#define CP_COMMIT() asm volatile("cp.async.commit_group;" ::: "memory")
#define CP_WAIT(n)  asm volatile("cp.async.wait_group %0;" :: "n"(n) : "memory")

// ================= phase kernels =================
// main-chain zero: g_h + g_cnt (27.2 MB)
__global__ void zero_main_kernel() {
    size_t tid = (size_t)blockIdx.x * blockDim.x + threadIdx.x;
    size_t stride = (size_t)gridDim.x * blockDim.x;
    float4 z = make_float4(0.f, 0.f, 0.f, 0.f);
    float4* h4 = reinterpret_cast<float4*>(g_h);
    for (size_t i = tid; i < (size_t)NN * HH / 4; i += stride) h4[i] = z;
    float4* c4 = reinterpret_cast<float4*>(g_cnt);
    for (size_t i = tid; i < (size_t)NN * RR / 4; i += stride) c4[i] = z;
}

// side-stream zero: g_agg (102.4 MB) — overlaps with count/scatter1
__global__ void zero_agg_kernel() {
    size_t tid = (size_t)blockIdx.x * blockDim.x + threadIdx.x;
    size_t stride = (size_t)gridDim.x * blockDim.x;
    float4 z = make_float4(0.f, 0.f, 0.f, 0.f);
    float4* a4 = reinterpret_cast<float4*>(g_agg);
    for (size_t i = tid; i < (size_t)RR * NN * HH / 8; i += stride) a4[i] = z;
}

// counts + packed edge index
__global__ void count_kernel(const int* __restrict__ ei, const int* __restrict__ et) {
    int e = blockIdx.x * blockDim.x + threadIdx.x;
    if (e < EE) {
        int src = ei[e];
        int dst = ei[EE + e];
        int r = et[e];
        int seg = dst * RR + r;
        g_eidx[e] = make_int2(src, seg);
        atomicAdd(&g_cnt[seg], 1.0f);
    }
}

// layer 1 scatter: cp.async-staged, 8 edges per warp
__global__ __launch_bounds__(256) void scatter1_kernel(const float* __restrict__ W1) {
    extern __shared__ char smem[];
    const int wid = threadIdx.x >> 5, lane = threadIdx.x & 31;
    char* buf = smem + wid * (8 * 512);
    const int e0 = (blockIdx.x * 8 + wid) * 8;

    int2 ev = g_eidx[e0 + (lane & 7)];
    float cw = (lane < 8) ? g_cnt[ev.y] : 1.0f;
    float winv = __frcp_rn(fmaxf(cw, 1.0f));

#pragma unroll
    for (int j = 0; j < 8; j++) {
        int srcj = __shfl_sync(0xffffffffu, ev.x, j);
        int segj = __shfl_sync(0xffffffffu, ev.y, j);
        const char* g = reinterpret_cast<const char*>(W1) +
                        ((size_t)(segj & 7) * NN + srcj) * (HH * 4) + lane * 16;
        cp_async16(smem_u32(buf + j * 512 + lane * 16), g);
    }
    CP_COMMIT();
    CP_WAIT(0);

#pragma unroll
    for (int j = 0; j < 8; j++) {
        int segj = __shfl_sync(0xffffffffu, ev.y, j);
        float wj = __shfl_sync(0xffffffffu, winv, j);
        float4 v = *reinterpret_cast<float4*>(buf + j * 512 + lane * 16);
        red4(g_h + (size_t)(segj >> 3) * HH + lane * 4,
             wj * v.x, wj * v.y, wj * v.z, wj * v.w);
    }
}

// fused: h = relu(g_h + root1 + b1) -> bf16 hi/lo split + fp16 copy
__global__ void fin1prepA_kernel(const float* __restrict__ root1, const float* __restrict__ b1) {
    int i = blockIdx.x * blockDim.x + threadIdx.x;
    if (i >= NN * HH / 4) return;
    float4 h = reinterpret_cast<const float4*>(g_h)[i];
    float4 r = reinterpret_cast<const float4*>(root1)[i];
    float4 b = reinterpret_cast<const float4*>(b1)[i & (HH / 4 - 1)];
    float x = fmaxf(h.x + r.x + b.x, 0.f);
    float y = fmaxf(h.y + r.y + b.y, 0.f);
    float z = fmaxf(h.z + r.z + b.z, 0.f);
    float w = fmaxf(h.w + r.w + b.w, 0.f);
    __nv_bfloat16 hx = __float2bfloat16(x), hy = __float2bfloat16(y);
    __nv_bfloat16 hz = __float2bfloat16(z), hw = __float2bfloat16(w);
    __nv_bfloat16 lx = __float2bfloat16(x - __bfloat162float(hx));
    __nv_bfloat16 ly = __float2bfloat16(y - __bfloat162float(hy));
    __nv_bfloat16 lz = __float2bfloat16(z - __bfloat162float(hz));
    __nv_bfloat16 lw = __float2bfloat16(w - __bfloat162float(hw));
    __nv_bfloat162 h0 = __halves2bfloat162(hx, hy), h1 = __halves2bfloat162(hz, hw);
    __nv_bfloat162 l0 = __halves2bfloat162(lx, ly), l1 = __halves2bfloat162(lz, lw);
    uint2 ph, pl;
    ph.x = *reinterpret_cast<uint32_t*>(&h0); ph.y = *reinterpret_cast<uint32_t*>(&h1);
    pl.x = *reinterpret_cast<uint32_t*>(&l0); pl.y = *reinterpret_cast<uint32_t*>(&l1);
    reinterpret_cast<uint2*>(g_Ahi)[i] = ph;
    reinterpret_cast<uint2*>(g_Alo)[i] = pl;
    __half2 f0 = __floats2half2_rn(x, y), f1 = __floats2half2_rn(z, w);
    uint2 pf;
    pf.x = *reinterpret_cast<uint32_t*>(&f0); pf.y = *reinterpret_cast<uint32_t*>(&f1);
    reinterpret_cast<uint2*>(g_h16)[i] = pf;
}

// W2 -> transposed f16 [z][n][k]; root2 -> transposed bf16 hi/lo
__global__ void prepB_kernel(const float* __restrict__ W2, const float* __restrict__ root2) {
    int idx = blockIdx.x * blockDim.x + threadIdx.x;
    if (idx >= 9 * HH * HH) return;
    int z = idx >> 14;
    int n = (idx >> 7) & 127;
    int k = idx & 127;
    if (z < RR) {
        float v = W2[((size_t)z << 14) + k * HH + n];
        g_Bf16[idx] = __float2half(v);
    } else {
        float v = root2[k * HH + n];
        __nv_bfloat16 hi = __float2bfloat16(v);
        g_Brh[n * HH + k] = hi;
        g_Brl[n * HH + k] = __float2bfloat16(v - __bfloat162float(hi));
    }
}

// layer 2 aggregate: agg[rel][dst] += w * h16[src]   (gathers L2-resident)
__global__ __launch_bounds__(256) void scatter2_kernel() {
    const int wid = threadIdx.x >> 5, lane = threadIdx.x & 31;
    const int e0 = (blockIdx.x * 8 + wid) * 16;
    int2 ev = g_eidx[e0 + (lane & 15)];
    float cw = g_cnt[ev.y];
    float winv = __frcp_rn(fmaxf(cw, 1.0f));
    __half2 wh2 = __floats2half2_rn(winv, winv);
    uint32_t wbits_own = *reinterpret_cast<uint32_t*>(&wh2);

    const int half_ = lane >> 4;
    const int q = lane & 15;

    int srcj[8], segj[8];
    uint32_t wb[8];
#pragma unroll
    for (int t = 0; t < 8; t++) {
        int esel = 2 * t + half_;
        srcj[t] = __shfl_sync(0xffffffffu, ev.x, esel);
        segj[t] = __shfl_sync(0xffffffffu, ev.y, esel);
        wb[t] = __shfl_sync(0xffffffffu, wbits_own, esel);
    }
    uint4 p[8];
#pragma unroll
    for (int t = 0; t < 8; t++)
        p[t] = __ldg(reinterpret_cast<const uint4*>(g_h16 + (size_t)srcj[t] * HH) + q);
#pragma unroll
    for (int t = 0; t < 8; t++) {
        __half2 w2 = *reinterpret_cast<__half2*>(&wb[t]);
        __half2 a = __hmul2(*reinterpret_cast<__half2*>(&p[t].x), w2);
        __half2 b = __hmul2(*reinterpret_cast<__half2*>(&p[t].y), w2);
        __half2 c = __hmul2(*reinterpret_cast<__half2*>(&p[t].z), w2);
        __half2 d = __hmul2(*reinterpret_cast<__half2*>(&p[t].w), w2);
        __half* dst = g_agg + ((size_t)(segj[t] & 7) * NN + (segj[t] >> 3)) * HH + q * 8;
        red4_h2(dst, *reinterpret_cast<uint32_t*>(&a), *reinterpret_cast<uint32_t*>(&b),
                *reinterpret_cast<uint32_t*>(&c), *reinterpret_cast<uint32_t*>(&d));
    }
}

// ================= HMMA GEMM: h2 = sum_r agg_r @ W2_r + h @ root2 + b2 =================
#define PITCH 136
#define PITCHB (PITCH * 2)
#define TILEB (128 * PITCHB)            // 34816 B
static constexpr int SM_RH = 0;                          // root A hi (bf16)
static constexpr int SM_RL = TILEB;                      // root A lo
static constexpr int SM_T0 = 2 * TILEB;                  // pair0 A / root B hi
static constexpr int SM_T1 = 3 * TILEB;                  // pair0 B / root B lo
static constexpr int SM_T2 = 4 * TILEB;                  // pair1 A
static constexpr int SM_T3 = 5 * TILEB;                  // pair1 B
static constexpr int SM_TOTAL = 6 * TILEB;               // 208896 B

__device__ __forceinline__ void stage_agg(char* smem, int bufA, int bufB, int z,
                                          int row0, int tid) {
#pragma unroll
    for (int i = 0; i < 8; i++) {
        int idx = tid + i * 256;
        int row = idx >> 4, seg = idx & 15;
        int gr = row0 + row; if (gr >= NN) gr = NN - 1;
        const char* srcA = reinterpret_cast<const char*>(g_agg) +
                           ((size_t)z * NN + gr) * (HH * 2) + seg * 16;
        cp_async16(smem_u32(smem + bufA + row * PITCHB + seg * 16), srcA);
        const char* srcB = reinterpret_cast<const char*>(g_Bf16) +
                           (size_t)z * (HH * HH * 2) + row * (HH * 2) + seg * 16;
        cp_async16(smem_u32(smem + bufB + row * PITCHB + seg * 16), srcB);
    }
}

__global__ __launch_bounds__(256, 1) void gemm_kernel(const float* __restrict__ b2) {
    extern __shared__ char smem[];
    uint32_t sb = smem_u32(smem);
    const int tid = threadIdx.x;
    const int wid = tid >> 5, lane = tid & 31;
    const int warp_m = (wid & 3) * 32;
    const int warp_n = (wid >> 2) * 64;
    const int row0 = blockIdx.x * 128;

    // group 0: root A (bf16 hi/lo)
#pragma unroll
    for (int i = 0; i < 8; i++) {
        int idx = tid + i * 256;
        int row = idx >> 4, seg = idx & 15;
        int gr = row0 + row; if (gr >= NN) gr = NN - 1;
        const char* Ah = reinterpret_cast<const char*>(g_Ahi) + (size_t)gr * (HH * 2) + seg * 16;
        const char* Al = reinterpret_cast<const char*>(g_Alo) + (size_t)gr * (HH * 2) + seg * 16;
        cp_async16(smem_u32(smem + SM_RH + row * PITCHB + seg * 16), Ah);
        cp_async16(smem_u32(smem + SM_RL + row * PITCHB + seg * 16), Al);
    }
    CP_COMMIT();
    // group 1: z=0 tiles into pair0
    stage_agg(smem, SM_T0, SM_T1, 0, row0, tid);
    CP_COMMIT();

    const uint32_t a_row = (uint32_t)(warp_m + (lane & 15));
    const uint32_t a_base = a_row * PITCHB + ((lane >> 4) << 3) * 2;
    const uint32_t b_n = (uint32_t)(warp_n + (lane & 7) + ((lane >> 4) << 3));
    const uint32_t b_base = b_n * PITCHB + (((lane >> 3) & 1) << 3) * 2;

    float acc[16][4];
#pragma unroll
    for (int i = 0; i < 16; i++)
#pragma unroll
        for (int j = 0; j < 4; j++) acc[i][j] = 0.f;

    // ---- 8 agg passes (f16 x f16) ----
    for (int z = 0; z < RR; z++) {
        const int curA = (z & 1) ? SM_T2 : SM_T0;
        const int curB = (z & 1) ? SM_T3 : SM_T1;
        if (z < RR - 1) {
            stage_agg(smem, (z & 1) ? SM_T0 : SM_T2, (z & 1) ? SM_T1 : SM_T3, z + 1, row0, tid);
            CP_COMMIT();
        } else {
            // stage root B hi/lo into pair0 (T0, T1)
#pragma unroll
            for (int i = 0; i < 8; i++) {
                int idx = tid + i * 256;
                int row = idx >> 4, seg = idx & 15;
                const char* Bh = reinterpret_cast<const char*>(g_Brh) + row * (HH * 2) + seg * 16;
                const char* Bl = reinterpret_cast<const char*>(g_Brl) + row * (HH * 2) + seg * 16;
                cp_async16(smem_u32(smem + SM_T0 + row * PITCHB + seg * 16), Bh);
                cp_async16(smem_u32(smem + SM_T1 + row * PITCHB + seg * 16), Bl);
            }
            CP_COMMIT();
        }
        CP_WAIT(1);
        __syncthreads();

#pragma unroll
        for (int k = 0; k < 8; k++) {
            const uint32_t koff = (uint32_t)(k * 32);
            uint32_t af[2][4];
#pragma unroll
            for (int mt = 0; mt < 2; mt++)
                ldsm4(af[mt], sb + curA + a_base + (uint32_t)(mt * 16) * PITCHB + koff);
            uint32_t bf[8][2];
#pragma unroll
            for (int ntp = 0; ntp < 4; ntp++) {
                uint32_t rh[4];
                ldsm4(rh, sb + curB + b_base + (uint32_t)(ntp * 16) * PITCHB + koff);
                bf[ntp * 2][0] = rh[0]; bf[ntp * 2][1] = rh[1];
                bf[ntp * 2 + 1][0] = rh[2]; bf[ntp * 2 + 1][1] = rh[3];
            }
#pragma unroll
            for (int mt = 0; mt < 2; mt++)
#pragma unroll
                for (int nt = 0; nt < 8; nt++)
                    mma_f16(acc[mt * 8 + nt], af[mt], bf[nt]);
        }
        __syncthreads();
    }

    // ---- root pass: 3 bf16 passes (hi*hi, lo*hi, hi*lo) ----
    CP_WAIT(0);
    __syncthreads();
#pragma unroll
    for (int p = 0; p < 3; p++) {
        const int aT = (p == 1) ? SM_RL : SM_RH;
        const int bT = (p == 2) ? SM_T1 : SM_T0;
#pragma unroll
        for (int k = 0; k < 8; k++) {
            const uint32_t koff = (uint32_t)(k * 32);
            uint32_t af[2][4];
#pragma unroll
            for (int mt = 0; mt < 2; mt++)
                ldsm4(af[mt], sb + aT + a_base + (uint32_t)(mt * 16) * PITCHB + koff);
            uint32_t bf[8][2];
#pragma unroll
            for (int ntp = 0; ntp < 4; ntp++) {
                uint32_t rh[4];
                ldsm4(rh, sb + bT + b_base + (uint32_t)(ntp * 16) * PITCHB + koff);
                bf[ntp * 2][0] = rh[0]; bf[ntp * 2][1] = rh[1];
                bf[ntp * 2 + 1][0] = rh[2]; bf[ntp * 2 + 1][1] = rh[3];
            }
#pragma unroll
            for (int mt = 0; mt < 2; mt++)
#pragma unroll
                for (int nt = 0; nt < 8; nt++)
                    mma_bf16(acc[mt * 8 + nt], af[mt], bf[nt]);
        }
    }

    // ---- single epilogue: h2 = acc + b2 ----
    const int erow = lane >> 2;
    const int ecol0 = (lane & 3) * 2;
#pragma unroll
    for (int mt = 0; mt < 2; mt++) {
        int r0 = row0 + warp_m + mt * 16 + erow;
        int r1 = r0 + 8;
        bool v0 = r0 < NN, v1 = r1 < NN;
#pragma unroll
        for (int nt = 0; nt < 8; nt++) {
            int c = warp_n + nt * 8 + ecol0;
            float bb0 = b2[c], bb1 = b2[c + 1];
            float* a4 = acc[mt * 8 + nt];
            if (v0) {
                float2 o = make_float2(a4[0] + bb0, a4[1] + bb1);
                *reinterpret_cast<float2*>(g_h2 + (size_t)r0 * HH + c) = o;
            }
            if (v1) {
                float2 o = make_float2(a4[2] + bb0, a4[3] + bb1);
                *reinterpret_cast<float2*>(g_h2 + (size_t)r1 * HH + c) = o;
            }
        }
    }
}

// out = relu(h2) @ lin_w + lin_b
__global__ void final_kernel(const float* __restrict__ lin_w, const float* __restrict__ lin_b,
                             float* __restrict__ out) {
    __shared__ float sw[HH * CC];
    __shared__ float sh[32][HH + 1];
    int tid = threadIdx.x;
    for (int i = tid; i < HH * CC; i += 256) sw[i] = lin_w[i];
    int n0 = blockIdx.x * 32;
    for (int i = tid; i < 32 * HH; i += 256) {
        int nl = i / HH, k = i % HH;
        int n = n0 + nl;
        sh[nl][k] = (n < NN) ? fmaxf(g_h2[(size_t)n * HH + k], 0.f) : 0.f;
    }
    __syncthreads();
#pragma unroll
    for (int j = 0; j < 5; j++) {
        int idx = tid + j * 256;
        int nl = idx / CC, c = idx % CC;
        float acc = lin_b[c];
#pragma unroll
        for (int k = 0; k < HH; k++) acc = fmaf(sh[nl][k], sw[k * CC + c], acc);
        int n = n0 + nl;
        if (n < NN) out[(size_t)n * CC + c] = acc;
    }
}

// ================= launch =================
extern "C" void kernel_launch(void* const* d_in, const int* in_sizes, int n_in,
                              void* d_out, int out_size) {
    const int* ei = (const int*)d_in[0];
    const int* et = (const int*)d_in[1];
    const float* W1 = (const float*)d_in[2];
    const float* root1 = (const float*)d_in[3];
    const float* b1 = (const float*)d_in[4];
    const float* W2 = (const float*)d_in[5];
    const float* root2 = (const float*)d_in[6];
    const float* b2 = (const float*)d_in[7];
    const float* lin_w = (const float*)d_in[8];
    const float* lin_b = (const float*)d_in[9];
    float* out = (float*)d_out;

    // streams/events created once, OUTSIDE graph capture (first call is the
    // uncaptured correctness run). No device memory is allocated here.
    static cudaStream_t s2 = nullptr;
    static cudaEvent_t evFork = nullptr, evSide = nullptr;
    if (!s2) {
        cudaStreamCreateWithFlags(&s2, cudaStreamNonBlocking);
        cudaEventCreateWithFlags(&evFork, cudaEventDisableTiming);
        cudaEventCreateWithFlags(&evSide, cudaEventDisableTiming);
    }

    cudaFuncSetAttribute(gemm_kernel, cudaFuncAttributeMaxDynamicSharedMemorySize, SM_TOTAL);

    // fork side branch: zero_agg (102 MB) + prepB run concurrently with the
    // count/scatter1/fin1prepA chain; joined before scatter2/gemm.
    cudaEventRecord(evFork, 0);
    cudaStreamWaitEvent(s2, evFork, 0);
    zero_agg_kernel<<<2048, 256, 0, s2>>>();
    prepB_kernel<<<(9 * HH * HH + 255) / 256, 256, 0, s2>>>(W2, root2);
    cudaEventRecord(evSide, s2);

    zero_main_kernel<<<1024, 256>>>();
    count_kernel<<<(EE + 255) / 256, 256>>>(ei, et);
    scatter1_kernel<<<EE / 64, 256, 32768>>>(W1);      // 8 edges/warp
    fin1prepA_kernel<<<(NN * HH / 4 + 255) / 256, 256>>>(root1, b1);

    cudaStreamWaitEvent(0, evSide, 0);                 // agg zeroed + Bf16 ready
    scatter2_kernel<<<EE / 128, 256>>>();              // 16 edges/warp, agg f16
    gemm_kernel<<<MTILES, 256, SM_TOTAL>>>(b2);
    final_kernel<<<(NN + 31) / 32, 256>>>(lin_w, lin_b, out);
}

// round 17
// speedup vs baseline: 2.0432x; 1.0870x over previous
#include <cuda_runtime.h>
#include <cuda_bf16.h>
#include <cuda_fp16.h>
#include <cstdint>

#define NN 50000
#define RR 8
#define HH 128
#define CC 40
#define EE 800000
#define MTILES 391     // ceil(NN/128)

// ---- scratch (device globals; no allocation allowed) ----
__device__ float g_cnt[NN * RR];                       // raw counts
__device__ int2 g_eidx[EE];                            // packed {src, dst*8+rel}
__device__ __half g_h16[(size_t)NN * HH];              // layer-1 f16 accumulator -> h table
__device__ __half g_agg[(size_t)RR * NN * HH];         // 102.4 MB: per-rel weighted sums (f16)
__device__ float g_h2[(size_t)NN * HH];
__device__ __nv_bfloat16 g_Ahi[(size_t)NN * HH];
__device__ __nv_bfloat16 g_Alo[(size_t)NN * HH];
__device__ __half g_Bf16[(size_t)RR * HH * HH];        // W2 transposed [z][n][k] f16
__device__ __nv_bfloat16 g_Brh[HH * HH];               // root2 transposed hi
__device__ __nv_bfloat16 g_Brl[HH * HH];               // root2 transposed lo

// ================= PTX helpers =================
__device__ __forceinline__ uint32_t smem_u32(const void* p) {
    uint32_t a;
    asm("{ .reg .u64 t; cvta.to.shared.u64 t, %1; cvt.u32.u64 %0, t; }" : "=r"(a) : "l"(p));
    return a;
}
__device__ __forceinline__ void red2_h2(void* p, uint32_t a, uint32_t b) {
    asm volatile("red.global.add.noftz.v2.f16x2 [%0], {%1,%2};"
                 :: "l"(p), "r"(a), "r"(b) : "memory");
}
__device__ __forceinline__ void red4_h2(void* p, uint32_t a, uint32_t b, uint32_t c, uint32_t d) {
    asm volatile("red.global.add.noftz.v4.f16x2 [%0], {%1,%2,%3,%4};"
                 :: "l"(p), "r"(a), "r"(b), "r"(c), "r"(d) : "memory");
}
__device__ __forceinline__ void ldsm4(uint32_t* r, uint32_t addr) {
    asm volatile("ldmatrix.sync.aligned.m8n8.x4.shared.b16 {%0,%1,%2,%3}, [%4];"
                 : "=r"(r[0]), "=r"(r[1]), "=r"(r[2]), "=r"(r[3]) : "r"(addr));
}
__device__ __forceinline__ void mma_bf16(float* d, const uint32_t* a, const uint32_t* b) {
    asm volatile(
        "mma.sync.aligned.m16n8k16.row.col.f32.bf16.bf16.f32 "
        "{%0,%1,%2,%3}, {%4,%5,%6,%7}, {%8,%9}, {%0,%1,%2,%3};"
        : "+f"(d[0]), "+f"(d[1]), "+f"(d[2]), "+f"(d[3])
        : "r"(a[0]), "r"(a[1]), "r"(a[2]), "r"(a[3]), "r"(b[0]), "r"(b[1]));
}
__device__ __forceinline__ void mma_f16(float* d, const uint32_t* a, const uint32_t* b) {
    asm volatile(
        "mma.sync.aligned.m16n8k16.row.col.f32.f16.f16.f32 "
        "{%0,%1,%2,%3}, {%4,%5,%6,%7}, {%8,%9}, {%0,%1,%2,%3};"
        : "+f"(d[0]), "+f"(d[1]), "+f"(d[2]), "+f"(d[3])
        : "r"(a[0]), "r"(a[1]), "r"(a[2]), "r"(a[3]), "r"(b[0]), "r"(b[1]));
}
__device__ __forceinline__ void cp_async16(uint32_t saddr, const void* gaddr) {
    asm volatile("cp.async.cg.shared.global [%0], [%1], 16;" :: "r"(saddr), "l"(gaddr));
}
#define CP_COMMIT() asm volatile("cp.async.commit_group;" ::: "memory")
#define CP_WAIT(n)  asm volatile("cp.async.wait_group %0;" :: "n"(n) : "memory")

// ================= phase kernels =================
// main-chain zero: g_h16 + g_cnt (14.4 MB)
__global__ void zero_main_kernel() {
    size_t tid = (size_t)blockIdx.x * blockDim.x + threadIdx.x;
    size_t stride = (size_t)gridDim.x * blockDim.x;
    float4 z = make_float4(0.f, 0.f, 0.f, 0.f);
    float4* h4 = reinterpret_cast<float4*>(g_h16);
    for (size_t i = tid; i < (size_t)NN * HH / 8; i += stride) h4[i] = z;
    float4* c4 = reinterpret_cast<float4*>(g_cnt);
    for (size_t i = tid; i < (size_t)NN * RR / 4; i += stride) c4[i] = z;
}

// side-stream zero: g_agg (102.4 MB) — overlaps with count/scatter1
__global__ void zero_agg_kernel() {
    size_t tid = (size_t)blockIdx.x * blockDim.x + threadIdx.x;
    size_t stride = (size_t)gridDim.x * blockDim.x;
    float4 z = make_float4(0.f, 0.f, 0.f, 0.f);
    float4* a4 = reinterpret_cast<float4*>(g_agg);
    for (size_t i = tid; i < (size_t)RR * NN * HH / 8; i += stride) a4[i] = z;
}

// counts + packed edge index
__global__ void count_kernel(const int* __restrict__ ei, const int* __restrict__ et) {
    int e = blockIdx.x * blockDim.x + threadIdx.x;
    if (e < EE) {
        int src = ei[e];
        int dst = ei[EE + e];
        int r = et[e];
        int seg = dst * RR + r;
        g_eidx[e] = make_int2(src, seg);
        atomicAdd(&g_cnt[seg], 1.0f);
    }
}

// layer 1 scatter: cp.async-staged, 8 edges per warp; f16 RED (8B/lane)
__global__ __launch_bounds__(256) void scatter1_kernel(const float* __restrict__ W1) {
    extern __shared__ char smem[];
    const int wid = threadIdx.x >> 5, lane = threadIdx.x & 31;
    char* buf = smem + wid * (8 * 512);
    const int e0 = (blockIdx.x * 8 + wid) * 8;

    int2 ev = g_eidx[e0 + (lane & 7)];
    float cw = (lane < 8) ? g_cnt[ev.y] : 1.0f;
    float winv = __frcp_rn(fmaxf(cw, 1.0f));

#pragma unroll
    for (int j = 0; j < 8; j++) {
        int srcj = __shfl_sync(0xffffffffu, ev.x, j);
        int segj = __shfl_sync(0xffffffffu, ev.y, j);
        const char* g = reinterpret_cast<const char*>(W1) +
                        ((size_t)(segj & 7) * NN + srcj) * (HH * 4) + lane * 16;
        cp_async16(smem_u32(buf + j * 512 + lane * 16), g);
    }
    CP_COMMIT();
    CP_WAIT(0);

#pragma unroll
    for (int j = 0; j < 8; j++) {
        int segj = __shfl_sync(0xffffffffu, ev.y, j);
        float wj = __shfl_sync(0xffffffffu, winv, j);
        float4 v = *reinterpret_cast<float4*>(buf + j * 512 + lane * 16);
        __half2 p0 = __floats2half2_rn(wj * v.x, wj * v.y);
        __half2 p1 = __floats2half2_rn(wj * v.z, wj * v.w);
        red2_h2(g_h16 + (size_t)(segj >> 3) * HH + lane * 4,
                *reinterpret_cast<uint32_t*>(&p0), *reinterpret_cast<uint32_t*>(&p1));
    }
}

// fused: h = relu(h16 + root1 + b1) -> bf16 hi/lo split + f16 table (in place)
__global__ void fin1prepA_kernel(const float* __restrict__ root1, const float* __restrict__ b1) {
    int i = blockIdx.x * blockDim.x + threadIdx.x;
    if (i >= NN * HH / 4) return;
    uint2 hp = reinterpret_cast<const uint2*>(g_h16)[i];
    float2 f01 = __half22float2(*reinterpret_cast<__half2*>(&hp.x));
    float2 f23 = __half22float2(*reinterpret_cast<__half2*>(&hp.y));
    float4 r = reinterpret_cast<const float4*>(root1)[i];
    float4 b = reinterpret_cast<const float4*>(b1)[i & (HH / 4 - 1)];
    float x = fmaxf(f01.x + r.x + b.x, 0.f);
    float y = fmaxf(f01.y + r.y + b.y, 0.f);
    float z = fmaxf(f23.x + r.z + b.z, 0.f);
    float w = fmaxf(f23.y + r.w + b.w, 0.f);
    __nv_bfloat16 hx = __float2bfloat16(x), hy = __float2bfloat16(y);
    __nv_bfloat16 hz = __float2bfloat16(z), hw = __float2bfloat16(w);
    __nv_bfloat16 lx = __float2bfloat16(x - __bfloat162float(hx));
    __nv_bfloat16 ly = __float2bfloat16(y - __bfloat162float(hy));
    __nv_bfloat16 lz = __float2bfloat16(z - __bfloat162float(hz));
    __nv_bfloat16 lw = __float2bfloat16(w - __bfloat162float(hw));
    __nv_bfloat162 h0 = __halves2bfloat162(hx, hy), h1 = __halves2bfloat162(hz, hw);
    __nv_bfloat162 l0 = __halves2bfloat162(lx, ly), l1 = __halves2bfloat162(lz, lw);
    uint2 ph, pl;
    ph.x = *reinterpret_cast<uint32_t*>(&h0); ph.y = *reinterpret_cast<uint32_t*>(&h1);
    pl.x = *reinterpret_cast<uint32_t*>(&l0); pl.y = *reinterpret_cast<uint32_t*>(&l1);
    reinterpret_cast<uint2*>(g_Ahi)[i] = ph;
    reinterpret_cast<uint2*>(g_Alo)[i] = pl;
    __half2 f0 = __floats2half2_rn(x, y), f1 = __floats2half2_rn(z, w);
    uint2 pf;
    pf.x = *reinterpret_cast<uint32_t*>(&f0); pf.y = *reinterpret_cast<uint32_t*>(&f1);
    reinterpret_cast<uint2*>(g_h16)[i] = pf;
}

// W2 -> transposed f16 [z][n][k]; root2 -> transposed bf16 hi/lo
__global__ void prepB_kernel(const float* __restrict__ W2, const float* __restrict__ root2) {
    int idx = blockIdx.x * blockDim.x + threadIdx.x;
    if (idx >= 9 * HH * HH) return;
    int z = idx >> 14;
    int n = (idx >> 7) & 127;
    int k = idx & 127;
    if (z < RR) {
        float v = W2[((size_t)z << 14) + k * HH + n];
        g_Bf16[idx] = __float2half(v);
    } else {
        float v = root2[k * HH + n];
        __nv_bfloat16 hi = __float2bfloat16(v);
        g_Brh[n * HH + k] = hi;
        g_Brl[n * HH + k] = __float2bfloat16(v - __bfloat162float(hi));
    }
}

// layer 2 aggregate: agg[rel][dst] += w * h16[src]   (gathers L2-resident)
__global__ __launch_bounds__(256) void scatter2_kernel() {
    const int wid = threadIdx.x >> 5, lane = threadIdx.x & 31;
    const int e0 = (blockIdx.x * 8 + wid) * 16;
    int2 ev = g_eidx[e0 + (lane & 15)];
    float cw = g_cnt[ev.y];
    float winv = __frcp_rn(fmaxf(cw, 1.0f));
    __half2 wh2 = __floats2half2_rn(winv, winv);
    uint32_t wbits_own = *reinterpret_cast<uint32_t*>(&wh2);

    const int half_ = lane >> 4;
    const int q = lane & 15;

    int srcj[8], segj[8];
    uint32_t wb[8];
#pragma unroll
    for (int t = 0; t < 8; t++) {
        int esel = 2 * t + half_;
        srcj[t] = __shfl_sync(0xffffffffu, ev.x, esel);
        segj[t] = __shfl_sync(0xffffffffu, ev.y, esel);
        wb[t] = __shfl_sync(0xffffffffu, wbits_own, esel);
    }
    uint4 p[8];
#pragma unroll
    for (int t = 0; t < 8; t++)
        p[t] = __ldg(reinterpret_cast<const uint4*>(g_h16 + (size_t)srcj[t] * HH) + q);
#pragma unroll
    for (int t = 0; t < 8; t++) {
        __half2 w2 = *reinterpret_cast<__half2*>(&wb[t]);
        __half2 a = __hmul2(*reinterpret_cast<__half2*>(&p[t].x), w2);
        __half2 b = __hmul2(*reinterpret_cast<__half2*>(&p[t].y), w2);
        __half2 c = __hmul2(*reinterpret_cast<__half2*>(&p[t].z), w2);
        __half2 d = __hmul2(*reinterpret_cast<__half2*>(&p[t].w), w2);
        __half* dst = g_agg + ((size_t)(segj[t] & 7) * NN + (segj[t] >> 3)) * HH + q * 8;
        red4_h2(dst, *reinterpret_cast<uint32_t*>(&a), *reinterpret_cast<uint32_t*>(&b),
                *reinterpret_cast<uint32_t*>(&c), *reinterpret_cast<uint32_t*>(&d));
    }
}

// ================= HMMA GEMM: h2 = sum_r agg_r @ W2_r + h @ root2 + b2 =================
#define PITCH 136
#define PITCHB (PITCH * 2)
#define TILEB (128 * PITCHB)            // 34816 B
static constexpr int SM_RH = 0;                          // root A hi (bf16)
static constexpr int SM_RL = TILEB;                      // root A lo
static constexpr int SM_T0 = 2 * TILEB;                  // pair0 A / root B hi
static constexpr int SM_T1 = 3 * TILEB;                  // pair0 B / root B lo
static constexpr int SM_T2 = 4 * TILEB;                  // pair1 A
static constexpr int SM_T3 = 5 * TILEB;                  // pair1 B
static constexpr int SM_TOTAL = 6 * TILEB;               // 208896 B

__device__ __forceinline__ void stage_agg(char* smem, int bufA, int bufB, int z,
                                          int row0, int tid) {
#pragma unroll
    for (int i = 0; i < 8; i++) {
        int idx = tid + i * 256;
        int row = idx >> 4, seg = idx & 15;
        int gr = row0 + row; if (gr >= NN) gr = NN - 1;
        const char* srcA = reinterpret_cast<const char*>(g_agg) +
                           ((size_t)z * NN + gr) * (HH * 2) + seg * 16;
        cp_async16(smem_u32(smem + bufA + row * PITCHB + seg * 16), srcA);
        const char* srcB = reinterpret_cast<const char*>(g_Bf16) +
                           (size_t)z * (HH * HH * 2) + row * (HH * 2) + seg * 16;
        cp_async16(smem_u32(smem + bufB + row * PITCHB + seg * 16), srcB);
    }
}

__global__ __launch_bounds__(256, 1) void gemm_kernel(const float* __restrict__ b2) {
    extern __shared__ char smem[];
    uint32_t sb = smem_u32(smem);
    const int tid = threadIdx.x;
    const int wid = tid >> 5, lane = tid & 31;
    const int warp_m = (wid & 3) * 32;
    const int warp_n = (wid >> 2) * 64;
    const int row0 = blockIdx.x * 128;

    // group 0: root A (bf16 hi/lo)
#pragma unroll
    for (int i = 0; i < 8; i++) {
        int idx = tid + i * 256;
        int row = idx >> 4, seg = idx & 15;
        int gr = row0 + row; if (gr >= NN) gr = NN - 1;
        const char* Ah = reinterpret_cast<const char*>(g_Ahi) + (size_t)gr * (HH * 2) + seg * 16;
        const char* Al = reinterpret_cast<const char*>(g_Alo) + (size_t)gr * (HH * 2) + seg * 16;
        cp_async16(smem_u32(smem + SM_RH + row * PITCHB + seg * 16), Ah);
        cp_async16(smem_u32(smem + SM_RL + row * PITCHB + seg * 16), Al);
    }
    CP_COMMIT();
    // group 1: z=0 tiles into pair0
    stage_agg(smem, SM_T0, SM_T1, 0, row0, tid);
    CP_COMMIT();

    const uint32_t a_row = (uint32_t)(warp_m + (lane & 15));
    const uint32_t a_base = a_row * PITCHB + ((lane >> 4) << 3) * 2;
    const uint32_t b_n = (uint32_t)(warp_n + (lane & 7) + ((lane >> 4) << 3));
    const uint32_t b_base = b_n * PITCHB + (((lane >> 3) & 1) << 3) * 2;

    float acc[16][4];
#pragma unroll
    for (int i = 0; i < 16; i++)
#pragma unroll
        for (int j = 0; j < 4; j++) acc[i][j] = 0.f;

    // ---- 8 agg passes (f16 x f16) ----
    for (int z = 0; z < RR; z++) {
        const int curA = (z & 1) ? SM_T2 : SM_T0;
        const int curB = (z & 1) ? SM_T3 : SM_T1;
        if (z < RR - 1) {
            stage_agg(smem, (z & 1) ? SM_T0 : SM_T2, (z & 1) ? SM_T1 : SM_T3, z + 1, row0, tid);
            CP_COMMIT();
        } else {
            // stage root B hi/lo into pair0 (T0, T1)
#pragma unroll
            for (int i = 0; i < 8; i++) {
                int idx = tid + i * 256;
                int row = idx >> 4, seg = idx & 15;
                const char* Bh = reinterpret_cast<const char*>(g_Brh) + row * (HH * 2) + seg * 16;
                const char* Bl = reinterpret_cast<const char*>(g_Brl) + row * (HH * 2) + seg * 16;
                cp_async16(smem_u32(smem + SM_T0 + row * PITCHB + seg * 16), Bh);
                cp_async16(smem_u32(smem + SM_T1 + row * PITCHB + seg * 16), Bl);
            }
            CP_COMMIT();
        }
        CP_WAIT(1);
        __syncthreads();

#pragma unroll
        for (int k = 0; k < 8; k++) {
            const uint32_t koff = (uint32_t)(k * 32);
            uint32_t af[2][4];
#pragma unroll
            for (int mt = 0; mt < 2; mt++)
                ldsm4(af[mt], sb + curA + a_base + (uint32_t)(mt * 16) * PITCHB + koff);
            uint32_t bf[8][2];
#pragma unroll
            for (int ntp = 0; ntp < 4; ntp++) {
                uint32_t rh[4];
                ldsm4(rh, sb + curB + b_base + (uint32_t)(ntp * 16) * PITCHB + koff);
                bf[ntp * 2][0] = rh[0]; bf[ntp * 2][1] = rh[1];
                bf[ntp * 2 + 1][0] = rh[2]; bf[ntp * 2 + 1][1] = rh[3];
            }
#pragma unroll
            for (int mt = 0; mt < 2; mt++)
#pragma unroll
                for (int nt = 0; nt < 8; nt++)
                    mma_f16(acc[mt * 8 + nt], af[mt], bf[nt]);
        }
        __syncthreads();
    }

    // ---- root pass: 3 bf16 passes (hi*hi, lo*hi, hi*lo) ----
    CP_WAIT(0);
    __syncthreads();
#pragma unroll
    for (int p = 0; p < 3; p++) {
        const int aT = (p == 1) ? SM_RL : SM_RH;
        const int bT = (p == 2) ? SM_T1 : SM_T0;
#pragma unroll
        for (int k = 0; k < 8; k++) {
            const uint32_t koff = (uint32_t)(k * 32);
            uint32_t af[2][4];
#pragma unroll
            for (int mt = 0; mt < 2; mt++)
                ldsm4(af[mt], sb + aT + a_base + (uint32_t)(mt * 16) * PITCHB + koff);
            uint32_t bf[8][2];
#pragma unroll
            for (int ntp = 0; ntp < 4; ntp++) {
                uint32_t rh[4];
                ldsm4(rh, sb + bT + b_base + (uint32_t)(ntp * 16) * PITCHB + koff);
                bf[ntp * 2][0] = rh[0]; bf[ntp * 2][1] = rh[1];
                bf[ntp * 2 + 1][0] = rh[2]; bf[ntp * 2 + 1][1] = rh[3];
            }
#pragma unroll
            for (int mt = 0; mt < 2; mt++)
#pragma unroll
                for (int nt = 0; nt < 8; nt++)
                    mma_bf16(acc[mt * 8 + nt], af[mt], bf[nt]);
        }
    }

    // ---- single epilogue: h2 = acc + b2 ----
    const int erow = lane >> 2;
    const int ecol0 = (lane & 3) * 2;
#pragma unroll
    for (int mt = 0; mt < 2; mt++) {
        int r0 = row0 + warp_m + mt * 16 + erow;
        int r1 = r0 + 8;
        bool v0 = r0 < NN, v1 = r1 < NN;
#pragma unroll
        for (int nt = 0; nt < 8; nt++) {
            int c = warp_n + nt * 8 + ecol0;
            float bb0 = b2[c], bb1 = b2[c + 1];
            float* a4 = acc[mt * 8 + nt];
            if (v0) {
                float2 o = make_float2(a4[0] + bb0, a4[1] + bb1);
                *reinterpret_cast<float2*>(g_h2 + (size_t)r0 * HH + c) = o;
            }
            if (v1) {
                float2 o = make_float2(a4[2] + bb0, a4[3] + bb1);
                *reinterpret_cast<float2*>(g_h2 + (size_t)r1 * HH + c) = o;
            }
        }
    }
}

// out = relu(h2) @ lin_w + lin_b
__global__ void final_kernel(const float* __restrict__ lin_w, const float* __restrict__ lin_b,
                             float* __restrict__ out) {
    __shared__ float sw[HH * CC];
    __shared__ float sh[32][HH + 1];
    int tid = threadIdx.x;
    for (int i = tid; i < HH * CC; i += 256) sw[i] = lin_w[i];
    int n0 = blockIdx.x * 32;
    for (int i = tid; i < 32 * HH; i += 256) {
        int nl = i / HH, k = i % HH;
        int n = n0 + nl;
        sh[nl][k] = (n < NN) ? fmaxf(g_h2[(size_t)n * HH + k], 0.f) : 0.f;
    }
    __syncthreads();
#pragma unroll
    for (int j = 0; j < 5; j++) {
        int idx = tid + j * 256;
        int nl = idx / CC, c = idx % CC;
        float acc = lin_b[c];
#pragma unroll
        for (int k = 0; k < HH; k++) acc = fmaf(sh[nl][k], sw[k * CC + c], acc);
        int n = n0 + nl;
        if (n < NN) out[(size_t)n * CC + c] = acc;
    }
}

// ================= launch =================
extern "C" void kernel_launch(void* const* d_in, const int* in_sizes, int n_in,
                              void* d_out, int out_size) {
    const int* ei = (const int*)d_in[0];
    const int* et = (const int*)d_in[1];
    const float* W1 = (const float*)d_in[2];
    const float* root1 = (const float*)d_in[3];
    const float* b1 = (const float*)d_in[4];
    const float* W2 = (const float*)d_in[5];
    const float* root2 = (const float*)d_in[6];
    const float* b2 = (const float*)d_in[7];
    const float* lin_w = (const float*)d_in[8];
    const float* lin_b = (const float*)d_in[9];
    float* out = (float*)d_out;

    static cudaStream_t s2 = nullptr;
    static cudaEvent_t evFork = nullptr, evSide = nullptr;
    if (!s2) {
        cudaStreamCreateWithFlags(&s2, cudaStreamNonBlocking);
        cudaEventCreateWithFlags(&evFork, cudaEventDisableTiming);
        cudaEventCreateWithFlags(&evSide, cudaEventDisableTiming);
    }

    cudaFuncSetAttribute(gemm_kernel, cudaFuncAttributeMaxDynamicSharedMemorySize, SM_TOTAL);

    // fork side branch: zero_agg (102 MB) + prepB overlap with count/scatter1
    cudaEventRecord(evFork, 0);
    cudaStreamWaitEvent(s2, evFork, 0);
    zero_agg_kernel<<<2048, 256, 0, s2>>>();
    prepB_kernel<<<(9 * HH * HH + 255) / 256, 256, 0, s2>>>(W2, root2);
    cudaEventRecord(evSide, s2);

    zero_main_kernel<<<1024, 256>>>();
    count_kernel<<<(EE + 255) / 256, 256>>>(ei, et);
    scatter1_kernel<<<EE / 64, 256, 32768>>>(W1);      // 8 edges/warp, f16 RED
    fin1prepA_kernel<<<(NN * HH / 4 + 255) / 256, 256>>>(root1, b1);

    cudaStreamWaitEvent(0, evSide, 0);                 // agg zeroed + Bf16 ready
    scatter2_kernel<<<EE / 128, 256>>>();              // 16 edges/warp, agg f16
    gemm_kernel<<<MTILES, 256, SM_TOTAL>>>(b2);
    final_kernel<<<(NN + 31) / 32, 256>>>(lin_w, lin_b, out);
}